// round 1
// baseline (speedup 1.0000x reference)
#include <cuda_runtime.h>
#include <cuda_bf16.h>

// ---------------- problem dims (fixed) ----------------
// QLEN=1024, BSZ=4, D_MODEL=1024, N_HEAD=16, D_HEAD=64
// tokens T = 4096 (row t = i*BSZ + b), z = b*16 + h (64 batch-heads)

#define QLEN 1024
#define BSZ 4
#define DM 1024
#define NH 16
#define DH 64
#define T_TOK 4096
#define NZ 64

// ---------------- scratch (device globals; no cudaMalloc allowed) ----------------
__device__ float g_wheads[(size_t)T_TOK * 3 * DM];          // 50 MB
__device__ float g_rkraw [(size_t)T_TOK * DM];              // 17 MB
__device__ float g_QW[(size_t)NZ * QLEN * DH];              // q + r_w_bias
__device__ float g_QR[(size_t)NZ * QLEN * DH];              // q + r_r_bias
__device__ float g_Kb[(size_t)NZ * QLEN * DH];
__device__ float g_Vb[(size_t)NZ * QLEN * DH];
__device__ float g_RK[(size_t)NZ * QLEN * DH];
__device__ float g_AC[(size_t)NZ * QLEN * QLEN + 2048];     // 256 MB (+pad for speculative reads)
__device__ float g_BD[(size_t)NZ * QLEN * QLEN + 2048];     // 256 MB (+pad)
__device__ float g_AV[(size_t)T_TOK * DM];
__device__ float g_AO[(size_t)T_TOK * DM];

// ---------------- generic fp32 GEMM:  C[M,N] = A[M,K] @ B[N,K]^T ----------------
// 128x128 tile, BK=16, 256 threads, 8x8 per thread. Optional batch strides
// (blockIdx.z) and triangle modes: tri=1 skip bx>by (AC), tri=2 skip bx+by<gridDim.x-1 (BD band).
#define BM 128
#define BN 128
#define BK 16

__global__ void __launch_bounds__(256) gemm_nt_kernel(
    const float* __restrict__ A, const float* __restrict__ B, float* __restrict__ C,
    int M, int N, int K, long long sA, long long sB, long long sC, int tri)
{
    int bx = blockIdx.x, by = blockIdx.y, z = blockIdx.z;
    if (tri == 1 && bx > by) return;
    if (tri == 2 && (bx + by) < (int)gridDim.x - 1) return;
    A += (long long)z * sA;
    B += (long long)z * sB;
    C += (long long)z * sC;

    __shared__ float As[BK][BM + 4];
    __shared__ float Bs[BK][BN + 4];

    int tid = threadIdx.x;
    int tx = tid & 15, ty = tid >> 4;
    const float* Ab = A + (long long)(by * BM) * K;
    const float* Bb = B + (long long)(bx * BN) * K;

    float acc[8][8];
#pragma unroll
    for (int u = 0; u < 8; u++)
#pragma unroll
        for (int v = 0; v < 8; v++) acc[u][v] = 0.f;

    for (int k0 = 0; k0 < K; k0 += BK) {
#pragma unroll
        for (int s = tid; s < 512; s += 256) {
            int row = s >> 2, kq = s & 3;
            float4 v = *(const float4*)(Ab + (long long)row * K + k0 + kq * 4);
            As[kq * 4 + 0][row] = v.x; As[kq * 4 + 1][row] = v.y;
            As[kq * 4 + 2][row] = v.z; As[kq * 4 + 3][row] = v.w;
        }
#pragma unroll
        for (int s = tid; s < 512; s += 256) {
            int row = s >> 2, kq = s & 3;
            float4 v = *(const float4*)(Bb + (long long)row * K + k0 + kq * 4);
            Bs[kq * 4 + 0][row] = v.x; Bs[kq * 4 + 1][row] = v.y;
            Bs[kq * 4 + 2][row] = v.z; Bs[kq * 4 + 3][row] = v.w;
        }
        __syncthreads();
#pragma unroll
        for (int kk = 0; kk < BK; kk++) {
            float ar[8], br[8];
#pragma unroll
            for (int u = 0; u < 8; u++) ar[u] = As[kk][ty * 8 + u];
#pragma unroll
            for (int v = 0; v < 8; v++) br[v] = Bs[kk][tx * 8 + v];
#pragma unroll
            for (int u = 0; u < 8; u++)
#pragma unroll
                for (int v = 0; v < 8; v++) acc[u][v] += ar[u] * br[v];
        }
        __syncthreads();
    }

    float* Cb = C + (long long)(by * BM + ty * 8) * N + bx * BN + tx * 8;
#pragma unroll
    for (int u = 0; u < 8; u++) {
        float4 w0 = make_float4(acc[u][0], acc[u][1], acc[u][2], acc[u][3]);
        float4 w1 = make_float4(acc[u][4], acc[u][5], acc[u][6], acc[u][7]);
        *(float4*)(Cb + (long long)u * N) = w0;
        *(float4*)(Cb + (long long)u * N + 4) = w1;
    }
}

// ---------------- split heads + biases ----------------
// QW/QR/Kb/Vb/RK layout: [z][i][d],  z = b*16 + h,  idx = ((z*1024)+i)*64+d
__global__ void __launch_bounds__(256) split_kernel(
    const float* __restrict__ wheads, const float* __restrict__ rkraw,
    const float* __restrict__ rwb, const float* __restrict__ rrb,
    float* __restrict__ QW, float* __restrict__ QR,
    float* __restrict__ Kb, float* __restrict__ Vb, float* __restrict__ RK)
{
    int idx = blockIdx.x * 256 + threadIdx.x;      // 2^22 total
    int d = idx & 63;
    int i = (idx >> 6) & 1023;
    int z = idx >> 16;
    int b = z >> 4, h = z & 15;
    long long t = (long long)i * BSZ + b;
    int hd = h * 64 + d;
    float q  = wheads[t * 3072 + hd];
    float k  = wheads[t * 3072 + 1024 + hd];
    float v  = wheads[t * 3072 + 2048 + hd];
    float rk = rkraw[t * 1024 + hd];
    QW[idx] = q + rwb[hd];
    QR[idx] = q + rrb[hd];
    Kb[idx] = k;
    Vb[idx] = v;
    RK[idx] = rk;
}

// ---------------- fused causal softmax + P@V with relative-shift gather ----------------
// grid = (8 i-tiles, 64 z), 256 threads.
// S mapping: thread (tx=tid&15, ty=tid>>4) owns S[i0+ty*8+a][j0+tx*8+b], 8x8.
// O mapping: same thread owns O[i0+ty*8+u][tx*4 .. tx*4+3].
__global__ void __launch_bounds__(256) attn_kernel(
    const float* __restrict__ AC, const float* __restrict__ BD,
    const float* __restrict__ Vb, float* __restrict__ AV)
{
    extern __shared__ float sm[];
    float* Ps = sm;                 // [128][132]
    float* Vs = sm + 128 * 132;     // [128][68]

    int it = blockIdx.x, z = blockIdx.y;
    int b = z >> 4, h = z & 15;
    const float* ACz = AC + (long long)z * (QLEN * QLEN);
    const float* BDz = BD + (long long)z * (QLEN * QLEN);
    const float* Vz  = Vb + (long long)z * (QLEN * DH);

    int tid = threadIdx.x, tx = tid & 15, ty = tid >> 4;
    int i0 = it << 7;

    float Oacc[8][4];
    float m_loc[8], l_loc[8];
#pragma unroll
    for (int u = 0; u < 8; u++) {
        m_loc[u] = -1e30f; l_loc[u] = 0.f;
        Oacc[u][0] = Oacc[u][1] = Oacc[u][2] = Oacc[u][3] = 0.f;
    }

    const float scale = 0.125f;   // 1/sqrt(64)

    for (int jt = 0; jt <= it; jt++) {
        int j0 = jt << 7;
        // cooperative V tile load: Vs[tj][d]
#pragma unroll
        for (int s2 = tid; s2 < 2048; s2 += 256) {
            int tj = s2 >> 4, dq = s2 & 15;
            *(float4*)(Vs + tj * 68 + dq * 4) =
                *(const float4*)(Vz + (long long)(j0 + tj) * DH + dq * 4);
        }

        float alpha[8];
#pragma unroll
        for (int a = 0; a < 8; a++) {
            int i = i0 + ty * 8 + a;
            const float* acp = ACz + (long long)i * QLEN + j0 + tx * 8;
            const float* bdp = BDz + (long long)i * QLEN + (j0 + tx * 8 - i + (QLEN - 1));
            float sv[8];
#pragma unroll
            for (int bb = 0; bb < 8; bb++) {
                int j = j0 + tx * 8 + bb;
                sv[bb] = (j <= i) ? (acp[bb] + bdp[bb]) * scale : -1e30f;
            }
            float mx = sv[0];
#pragma unroll
            for (int bb = 1; bb < 8; bb++) mx = fmaxf(mx, sv[bb]);
#pragma unroll
            for (int off = 8; off >= 1; off >>= 1)
                mx = fmaxf(mx, __shfl_xor_sync(0xffffffffu, mx, off, 16));
            float mold = m_loc[a];
            float mnew = fmaxf(mold, mx);
            float al = __expf(mold - mnew);
            float ps = 0.f;
#pragma unroll
            for (int bb = 0; bb < 8; bb++) {
                float p = __expf(sv[bb] - mnew);
                sv[bb] = p; ps += p;
            }
#pragma unroll
            for (int off = 8; off >= 1; off >>= 1)
                ps += __shfl_xor_sync(0xffffffffu, ps, off, 16);
            m_loc[a] = mnew;
            l_loc[a] = l_loc[a] * al + ps;
            alpha[a] = al;
            *(float4*)(Ps + (ty * 8 + a) * 132 + tx * 8) =
                make_float4(sv[0], sv[1], sv[2], sv[3]);
            *(float4*)(Ps + (ty * 8 + a) * 132 + tx * 8 + 4) =
                make_float4(sv[4], sv[5], sv[6], sv[7]);
        }
        __syncthreads();

        // rescale + P@V
#pragma unroll
        for (int u = 0; u < 8; u++) {
            float al = alpha[u];
            Oacc[u][0] *= al; Oacc[u][1] *= al; Oacc[u][2] *= al; Oacc[u][3] *= al;
        }
#pragma unroll 4
        for (int tj = 0; tj < 128; tj++) {
            float4 vv = *(const float4*)(Vs + tj * 68 + tx * 4);
#pragma unroll
            for (int u = 0; u < 8; u++) {
                float p = Ps[(ty * 8 + u) * 132 + tj];
                Oacc[u][0] += p * vv.x; Oacc[u][1] += p * vv.y;
                Oacc[u][2] += p * vv.z; Oacc[u][3] += p * vv.w;
            }
        }
        __syncthreads();
    }

#pragma unroll
    for (int u = 0; u < 8; u++) {
        int i = i0 + ty * 8 + u;
        float inv = 1.f / l_loc[u];
        long long t = (long long)i * BSZ + b;
        float4 o = make_float4(Oacc[u][0] * inv, Oacc[u][1] * inv,
                               Oacc[u][2] * inv, Oacc[u][3] * inv);
        *(float4*)(AV + t * DM + h * 64 + tx * 4) = o;
    }
}

// ---------------- residual + layernorm ----------------
__global__ void __launch_bounds__(256) ln_kernel(
    const float* __restrict__ w, const float* __restrict__ ao,
    const float* __restrict__ g, const float* __restrict__ be,
    float* __restrict__ out)
{
    long long t = blockIdx.x;
    int tid = threadIdx.x;
    __shared__ float red[8];
    __shared__ float s_mu, s_rstd;

    float4 wx = *(const float4*)(w  + t * DM + tid * 4);
    float4 ax = *(const float4*)(ao + t * DM + tid * 4);
    float x0 = wx.x + ax.x, x1 = wx.y + ax.y, x2 = wx.z + ax.z, x3 = wx.w + ax.w;

    float s = x0 + x1 + x2 + x3;
#pragma unroll
    for (int off = 16; off >= 1; off >>= 1) s += __shfl_xor_sync(0xffffffffu, s, off);
    if ((tid & 31) == 0) red[tid >> 5] = s;
    __syncthreads();
    if (tid == 0) {
        float a = 0;
#pragma unroll
        for (int i2 = 0; i2 < 8; i2++) a += red[i2];
        s_mu = a * (1.f / DM);
    }
    __syncthreads();
    float mu = s_mu;
    float d0 = x0 - mu, d1 = x1 - mu, d2 = x2 - mu, d3 = x3 - mu;
    float v = d0 * d0 + d1 * d1 + d2 * d2 + d3 * d3;
#pragma unroll
    for (int off = 16; off >= 1; off >>= 1) v += __shfl_xor_sync(0xffffffffu, v, off);
    if ((tid & 31) == 0) red[tid >> 5] = v;
    __syncthreads();
    if (tid == 0) {
        float a = 0;
#pragma unroll
        for (int i2 = 0; i2 < 8; i2++) a += red[i2];
        s_rstd = rsqrtf(a * (1.f / DM) + 1e-5f);
    }
    __syncthreads();
    float rs = s_rstd;
    float4 gg = *(const float4*)(g  + tid * 4);
    float4 bb = *(const float4*)(be + tid * 4);
    float4 o = make_float4(d0 * rs * gg.x + bb.x, d1 * rs * gg.y + bb.y,
                           d2 * rs * gg.z + bb.z, d3 * rs * gg.w + bb.w);
    *(float4*)(out + t * DM + tid * 4) = o;
}

// ---------------- host launcher ----------------
extern "C" void kernel_launch(void* const* d_in, const int* in_sizes, int n_in,
                              void* d_out, int out_size)
{
    const float* w       = (const float*)d_in[0];
    const float* r       = (const float*)d_in[1];
    const float* rwb     = (const float*)d_in[2];
    const float* rrb     = (const float*)d_in[3];
    const float* qkv_w   = (const float*)d_in[4];
    const float* r_net_w = (const float*)d_in[5];
    const float* o_w     = (const float*)d_in[6];
    const float* gamma   = (const float*)d_in[7];
    const float* beta    = (const float*)d_in[8];
    // d_in[9] = attn_mask: deterministic causal triu, handled analytically.
    float* out = (float*)d_out;

    float *wheads, *rkraw, *QW, *QR, *Kb, *Vb, *RK, *AC, *BD, *AV, *AO;
    cudaGetSymbolAddress((void**)&wheads, g_wheads);
    cudaGetSymbolAddress((void**)&rkraw,  g_rkraw);
    cudaGetSymbolAddress((void**)&QW, g_QW);
    cudaGetSymbolAddress((void**)&QR, g_QR);
    cudaGetSymbolAddress((void**)&Kb, g_Kb);
    cudaGetSymbolAddress((void**)&Vb, g_Vb);
    cudaGetSymbolAddress((void**)&RK, g_RK);
    cudaGetSymbolAddress((void**)&AC, g_AC);
    cudaGetSymbolAddress((void**)&BD, g_BD);
    cudaGetSymbolAddress((void**)&AV, g_AV);
    cudaGetSymbolAddress((void**)&AO, g_AO);

    const int ATTN_SMEM = (128 * 132 + 128 * 68) * 4;   // 102400 B
    cudaFuncSetAttribute(attn_kernel, cudaFuncAttributeMaxDynamicSharedMemorySize, ATTN_SMEM);

    // 1) w_heads = w @ qkv_w^T   [4096 x 3072]
    gemm_nt_kernel<<<dim3(3072 / BN, T_TOK / BM, 1), 256>>>(
        w, qkv_w, wheads, T_TOK, 3072, DM, 0, 0, 0, 0);
    // 2) r_head_k = r @ r_net_w^T   [4096 x 1024]
    gemm_nt_kernel<<<dim3(DM / BN, T_TOK / BM, 1), 256>>>(
        r, r_net_w, rkraw, T_TOK, DM, DM, 0, 0, 0, 0);
    // 3) split + biases
    split_kernel<<<(NZ * QLEN * DH) / 256, 256>>>(wheads, rkraw, rwb, rrb, QW, QR, Kb, Vb, RK);
    // 4) AC[z,i,j] = (q+rwb) . k   batched, lower-triangle tiles only
    gemm_nt_kernel<<<dim3(QLEN / BN, QLEN / BM, NZ), 256>>>(
        QW, Kb, AC, QLEN, QLEN, DH,
        (long long)QLEN * DH, (long long)QLEN * DH, (long long)QLEN * QLEN, 1);
    // 5) BD[z,i,m] = (q+rrb) . rk   batched, band tiles only
    gemm_nt_kernel<<<dim3(QLEN / BN, QLEN / BM, NZ), 256>>>(
        QR, RK, BD, QLEN, QLEN, DH,
        (long long)QLEN * DH, (long long)QLEN * DH, (long long)QLEN * QLEN, 2);
    // 6) causal softmax (with rel-shift gather) + P@V
    attn_kernel<<<dim3(QLEN / 128, NZ), 256, ATTN_SMEM>>>(AC, BD, Vb, AV);
    // 7) attn_out = AV @ o_w^T
    gemm_nt_kernel<<<dim3(DM / BN, T_TOK / BM, 1), 256>>>(
        AV, o_w, AO, T_TOK, DM, DM, 0, 0, 0, 0);
    // 8) residual + layernorm -> out
    ln_kernel<<<T_TOK, 256>>>(w, AO, gamma, beta, out);
}

// round 4
// speedup vs baseline: 2.1631x; 2.1631x over previous
#include <cuda_runtime.h>
#include <cuda_bf16.h>

// ---------------- problem dims (fixed) ----------------
#define QLEN 1024
#define BSZ 4
#define DM 1024
#define NH 16
#define DH 64
#define T_TOK 4096
#define NZ 64

// ---------------- scratch (device globals; no cudaMalloc allowed) ----------------
__device__ float g_wheads[(size_t)T_TOK * 3 * DM];
__device__ float g_rkraw [(size_t)T_TOK * DM];
__device__ float g_QW[(size_t)NZ * QLEN * DH];
__device__ float g_QR[(size_t)NZ * QLEN * DH];
__device__ float g_Kb[(size_t)NZ * QLEN * DH];
__device__ float g_Vb[(size_t)NZ * QLEN * DH];
__device__ float g_RK[(size_t)NZ * QLEN * DH];
__device__ float g_AC[(size_t)NZ * QLEN * QLEN + 2048];
__device__ float g_BD[(size_t)NZ * QLEN * QLEN + 2048];
__device__ float g_AV[(size_t)T_TOK * DM];
__device__ float g_AO[(size_t)T_TOK * DM];

// ---------------- tf32 helpers ----------------
__device__ __forceinline__ unsigned f2tf32(float x) {
    unsigned r;
    asm("cvt.rna.tf32.f32 %0, %1;" : "=r"(r) : "f"(x));
    return r;
}

// ---------------- mma.sync tf32 GEMM: C[M,N] = A[M,K] @ B[N,K]^T ----------------
// 128x128 CTA tile, BK=32, 256 threads = 8 warps (4 in M x 2 in N), warp tile 32x64.
// m16n8k8 tf32 MMA, fp32 accumulators. Smem stride 36 floats -> fragment LDS
// bank index = (4r+c)&31 = lane -> conflict-free.
// tri=1: skip bx>by (AC lower triangle). tri=2: skip bx+by<gridDim.x-1 (BD band).
#define SSTRIDE 36

__global__ void __launch_bounds__(256) gemm_mma_kernel(
    const float* __restrict__ A, const float* __restrict__ B, float* __restrict__ C,
    int M, int N, int K, long long sA, long long sB, long long sC, int tri)
{
    int bx = blockIdx.x, by = blockIdx.y, z = blockIdx.z;
    if (tri == 1 && bx > by) return;
    if (tri == 2 && (bx + by) < (int)gridDim.x - 1) return;

    __shared__ unsigned As[128 * SSTRIDE];
    __shared__ unsigned Bs[128 * SSTRIDE];

    int tid = threadIdx.x;
    int wid = tid >> 5, lane = tid & 31;
    int warp_m = wid & 3;        // 0..3  (M tiles of 32)
    int warp_n = wid >> 2;       // 0..1  (N tiles of 64)
    int r = lane >> 2, cc = lane & 3;

    const float* Ab = A + (long long)z * sA + (long long)(by * 128) * K;
    const float* Bb = B + (long long)z * sB + (long long)(bx * 128) * K;

    float acc[2][8][4];
#pragma unroll
    for (int mi = 0; mi < 2; mi++)
#pragma unroll
        for (int ni = 0; ni < 8; ni++)
#pragma unroll
            for (int q = 0; q < 4; q++) acc[mi][ni][q] = 0.f;

    for (int k0 = 0; k0 < K; k0 += 32) {
        // stage + convert to tf32 (RN)
#pragma unroll
        for (int s = tid; s < 1024; s += 256) {
            int row = s >> 3, q = s & 7;
            float4 va = *(const float4*)(Ab + (long long)row * K + k0 + q * 4);
            uint4 ua = make_uint4(f2tf32(va.x), f2tf32(va.y), f2tf32(va.z), f2tf32(va.w));
            *(uint4*)(As + row * SSTRIDE + q * 4) = ua;
            float4 vb = *(const float4*)(Bb + (long long)row * K + k0 + q * 4);
            uint4 ub = make_uint4(f2tf32(vb.x), f2tf32(vb.y), f2tf32(vb.z), f2tf32(vb.w));
            *(uint4*)(Bs + row * SSTRIDE + q * 4) = ub;
        }
        __syncthreads();

#pragma unroll
        for (int ks = 0; ks < 4; ks++) {
            int kb = ks * 8;
            unsigned a[2][4];
#pragma unroll
            for (int mi = 0; mi < 2; mi++) {
                int m0 = warp_m * 32 + mi * 16;
                a[mi][0] = As[(m0 + r)     * SSTRIDE + kb + cc];
                a[mi][1] = As[(m0 + 8 + r) * SSTRIDE + kb + cc];
                a[mi][2] = As[(m0 + r)     * SSTRIDE + kb + cc + 4];
                a[mi][3] = As[(m0 + 8 + r) * SSTRIDE + kb + cc + 4];
            }
#pragma unroll
            for (int ni = 0; ni < 8; ni++) {
                int n0 = warp_n * 64 + ni * 8;
                unsigned b0 = Bs[(n0 + r) * SSTRIDE + kb + cc];
                unsigned b1 = Bs[(n0 + r) * SSTRIDE + kb + cc + 4];
#pragma unroll
                for (int mi = 0; mi < 2; mi++) {
                    asm volatile(
                        "mma.sync.aligned.m16n8k8.row.col.f32.tf32.tf32.f32 "
                        "{%0,%1,%2,%3}, {%4,%5,%6,%7}, {%8,%9}, {%0,%1,%2,%3};"
                        : "+f"(acc[mi][ni][0]), "+f"(acc[mi][ni][1]),
                          "+f"(acc[mi][ni][2]), "+f"(acc[mi][ni][3])
                        : "r"(a[mi][0]), "r"(a[mi][1]), "r"(a[mi][2]), "r"(a[mi][3]),
                          "r"(b0), "r"(b1));
                }
            }
        }
        __syncthreads();
    }

    // epilogue: direct global stores (float2 per fragment row)
    float* Cb = C + (long long)z * sC;
#pragma unroll
    for (int mi = 0; mi < 2; mi++) {
        int m = by * 128 + warp_m * 32 + mi * 16 + r;
#pragma unroll
        for (int ni = 0; ni < 8; ni++) {
            int n = bx * 128 + warp_n * 64 + ni * 8 + cc * 2;
            *(float2*)(Cb + (long long)m * N + n) =
                make_float2(acc[mi][ni][0], acc[mi][ni][1]);
            *(float2*)(Cb + (long long)(m + 8) * N + n) =
                make_float2(acc[mi][ni][2], acc[mi][ni][3]);
        }
    }
}

// ---------------- split heads + biases ----------------
__global__ void __launch_bounds__(256) split_kernel(
    const float* __restrict__ wheads, const float* __restrict__ rkraw,
    const float* __restrict__ rwb, const float* __restrict__ rrb,
    float* __restrict__ QW, float* __restrict__ QR,
    float* __restrict__ Kb, float* __restrict__ Vb, float* __restrict__ RK)
{
    int idx = blockIdx.x * 256 + threadIdx.x;
    int d = idx & 63;
    int i = (idx >> 6) & 1023;
    int z = idx >> 16;
    int b = z >> 4, h = z & 15;
    long long t = (long long)i * BSZ + b;
    int hd = h * 64 + d;
    float q  = wheads[t * 3072 + hd];
    float k  = wheads[t * 3072 + 1024 + hd];
    float v  = wheads[t * 3072 + 2048 + hd];
    float rk = rkraw[t * 1024 + hd];
    QW[idx] = q + rwb[hd];
    QR[idx] = q + rrb[hd];
    Kb[idx] = k;
    Vb[idx] = v;
    RK[idx] = rk;
}

// ---------------- fused causal softmax + P@V with relative-shift gather ----------------
__global__ void __launch_bounds__(256) attn_kernel(
    const float* __restrict__ AC, const float* __restrict__ BD,
    const float* __restrict__ Vb, float* __restrict__ AV)
{
    extern __shared__ float sm[];
    float* Ps = sm;                 // [128][132]
    float* Vs = sm + 128 * 132;     // [128][68]

    int it = blockIdx.x, z = blockIdx.y;
    int b = z >> 4, h = z & 15;
    const float* ACz = AC + (long long)z * (QLEN * QLEN);
    const float* BDz = BD + (long long)z * (QLEN * QLEN);
    const float* Vz  = Vb + (long long)z * (QLEN * DH);

    int tid = threadIdx.x, tx = tid & 15, ty = tid >> 4;
    int i0 = it << 7;

    float Oacc[8][4];
    float m_loc[8], l_loc[8];
#pragma unroll
    for (int u = 0; u < 8; u++) {
        m_loc[u] = -1e30f; l_loc[u] = 0.f;
        Oacc[u][0] = Oacc[u][1] = Oacc[u][2] = Oacc[u][3] = 0.f;
    }

    const float scale = 0.125f;

    for (int jt = 0; jt <= it; jt++) {
        int j0 = jt << 7;
#pragma unroll
        for (int s2 = tid; s2 < 2048; s2 += 256) {
            int tj = s2 >> 4, dq = s2 & 15;
            *(float4*)(Vs + tj * 68 + dq * 4) =
                *(const float4*)(Vz + (long long)(j0 + tj) * DH + dq * 4);
        }

        float alpha[8];
#pragma unroll
        for (int a = 0; a < 8; a++) {
            int i = i0 + ty * 8 + a;
            const float* acp = ACz + (long long)i * QLEN + j0 + tx * 8;
            const float* bdp = BDz + (long long)i * QLEN + (j0 + tx * 8 - i + (QLEN - 1));
            float sv[8];
#pragma unroll
            for (int bb = 0; bb < 8; bb++) {
                int j = j0 + tx * 8 + bb;
                sv[bb] = (j <= i) ? (acp[bb] + bdp[bb]) * scale : -1e30f;
            }
            float mx = sv[0];
#pragma unroll
            for (int bb = 1; bb < 8; bb++) mx = fmaxf(mx, sv[bb]);
#pragma unroll
            for (int off = 8; off >= 1; off >>= 1)
                mx = fmaxf(mx, __shfl_xor_sync(0xffffffffu, mx, off, 16));
            float mold = m_loc[a];
            float mnew = fmaxf(mold, mx);
            float al = __expf(mold - mnew);
            float ps = 0.f;
#pragma unroll
            for (int bb = 0; bb < 8; bb++) {
                float p = __expf(sv[bb] - mnew);
                sv[bb] = p; ps += p;
            }
#pragma unroll
            for (int off = 8; off >= 1; off >>= 1)
                ps += __shfl_xor_sync(0xffffffffu, ps, off, 16);
            m_loc[a] = mnew;
            l_loc[a] = l_loc[a] * al + ps;
            alpha[a] = al;
            *(float4*)(Ps + (ty * 8 + a) * 132 + tx * 8) =
                make_float4(sv[0], sv[1], sv[2], sv[3]);
            *(float4*)(Ps + (ty * 8 + a) * 132 + tx * 8 + 4) =
                make_float4(sv[4], sv[5], sv[6], sv[7]);
        }
        __syncthreads();

#pragma unroll
        for (int u = 0; u < 8; u++) {
            float al = alpha[u];
            Oacc[u][0] *= al; Oacc[u][1] *= al; Oacc[u][2] *= al; Oacc[u][3] *= al;
        }
#pragma unroll 4
        for (int tj = 0; tj < 128; tj++) {
            float4 vv = *(const float4*)(Vs + tj * 68 + tx * 4);
#pragma unroll
            for (int u = 0; u < 8; u++) {
                float p = Ps[(ty * 8 + u) * 132 + tj];
                Oacc[u][0] += p * vv.x; Oacc[u][1] += p * vv.y;
                Oacc[u][2] += p * vv.z; Oacc[u][3] += p * vv.w;
            }
        }
        __syncthreads();
    }

#pragma unroll
    for (int u = 0; u < 8; u++) {
        int i = i0 + ty * 8 + u;
        float inv = 1.f / l_loc[u];
        long long t = (long long)i * BSZ + b;
        float4 o = make_float4(Oacc[u][0] * inv, Oacc[u][1] * inv,
                               Oacc[u][2] * inv, Oacc[u][3] * inv);
        *(float4*)(AV + t * DM + h * 64 + tx * 4) = o;
    }
}

// ---------------- residual + layernorm ----------------
__global__ void __launch_bounds__(256) ln_kernel(
    const float* __restrict__ w, const float* __restrict__ ao,
    const float* __restrict__ g, const float* __restrict__ be,
    float* __restrict__ out)
{
    long long t = blockIdx.x;
    int tid = threadIdx.x;
    __shared__ float red[8];
    __shared__ float s_mu, s_rstd;

    float4 wx = *(const float4*)(w  + t * DM + tid * 4);
    float4 ax = *(const float4*)(ao + t * DM + tid * 4);
    float x0 = wx.x + ax.x, x1 = wx.y + ax.y, x2 = wx.z + ax.z, x3 = wx.w + ax.w;

    float s = x0 + x1 + x2 + x3;
#pragma unroll
    for (int off = 16; off >= 1; off >>= 1) s += __shfl_xor_sync(0xffffffffu, s, off);
    if ((tid & 31) == 0) red[tid >> 5] = s;
    __syncthreads();
    if (tid == 0) {
        float a = 0;
#pragma unroll
        for (int i2 = 0; i2 < 8; i2++) a += red[i2];
        s_mu = a * (1.f / DM);
    }
    __syncthreads();
    float mu = s_mu;
    float d0 = x0 - mu, d1 = x1 - mu, d2 = x2 - mu, d3 = x3 - mu;
    float v = d0 * d0 + d1 * d1 + d2 * d2 + d3 * d3;
#pragma unroll
    for (int off = 16; off >= 1; off >>= 1) v += __shfl_xor_sync(0xffffffffu, v, off);
    if ((tid & 31) == 0) red[tid >> 5] = v;
    __syncthreads();
    if (tid == 0) {
        float a = 0;
#pragma unroll
        for (int i2 = 0; i2 < 8; i2++) a += red[i2];
        s_rstd = rsqrtf(a * (1.f / DM) + 1e-5f);
    }
    __syncthreads();
    float rs = s_rstd;
    float4 gg = *(const float4*)(g  + tid * 4);
    float4 bb = *(const float4*)(be + tid * 4);
    float4 o = make_float4(d0 * rs * gg.x + bb.x, d1 * rs * gg.y + bb.y,
                           d2 * rs * gg.z + bb.z, d3 * rs * gg.w + bb.w);
    *(float4*)(out + t * DM + tid * 4) = o;
}

// ---------------- host launcher ----------------
extern "C" void kernel_launch(void* const* d_in, const int* in_sizes, int n_in,
                              void* d_out, int out_size)
{
    const float* w       = (const float*)d_in[0];
    const float* r       = (const float*)d_in[1];
    const float* rwb     = (const float*)d_in[2];
    const float* rrb     = (const float*)d_in[3];
    const float* qkv_w   = (const float*)d_in[4];
    const float* r_net_w = (const float*)d_in[5];
    const float* o_w     = (const float*)d_in[6];
    const float* gamma   = (const float*)d_in[7];
    const float* beta    = (const float*)d_in[8];
    float* out = (float*)d_out;

    float *wheads, *rkraw, *QW, *QR, *Kb, *Vb, *RK, *AC, *BD, *AV, *AO;
    cudaGetSymbolAddress((void**)&wheads, g_wheads);
    cudaGetSymbolAddress((void**)&rkraw,  g_rkraw);
    cudaGetSymbolAddress((void**)&QW, g_QW);
    cudaGetSymbolAddress((void**)&QR, g_QR);
    cudaGetSymbolAddress((void**)&Kb, g_Kb);
    cudaGetSymbolAddress((void**)&Vb, g_Vb);
    cudaGetSymbolAddress((void**)&RK, g_RK);
    cudaGetSymbolAddress((void**)&AC, g_AC);
    cudaGetSymbolAddress((void**)&BD, g_BD);
    cudaGetSymbolAddress((void**)&AV, g_AV);
    cudaGetSymbolAddress((void**)&AO, g_AO);

    const int ATTN_SMEM = (128 * 132 + 128 * 68) * 4;
    cudaFuncSetAttribute(attn_kernel, cudaFuncAttributeMaxDynamicSharedMemorySize, ATTN_SMEM);

    // 1) w_heads = w @ qkv_w^T   [4096 x 3072]
    gemm_mma_kernel<<<dim3(3072 / 128, T_TOK / 128, 1), 256>>>(
        w, qkv_w, wheads, T_TOK, 3072, DM, 0, 0, 0, 0);
    // 2) r_head_k = r @ r_net_w^T   [4096 x 1024]
    gemm_mma_kernel<<<dim3(DM / 128, T_TOK / 128, 1), 256>>>(
        r, r_net_w, rkraw, T_TOK, DM, DM, 0, 0, 0, 0);
    // 3) split + biases
    split_kernel<<<(NZ * QLEN * DH) / 256, 256>>>(wheads, rkraw, rwb, rrb, QW, QR, Kb, Vb, RK);
    // 4) AC = (q+rwb) . k   batched, lower-triangle tiles
    gemm_mma_kernel<<<dim3(QLEN / 128, QLEN / 128, NZ), 256>>>(
        QW, Kb, AC, QLEN, QLEN, DH,
        (long long)QLEN * DH, (long long)QLEN * DH, (long long)QLEN * QLEN, 1);
    // 5) BD = (q+rrb) . rk   batched, band tiles
    gemm_mma_kernel<<<dim3(QLEN / 128, QLEN / 128, NZ), 256>>>(
        QR, RK, BD, QLEN, QLEN, DH,
        (long long)QLEN * DH, (long long)QLEN * DH, (long long)QLEN * QLEN, 2);
    // 6) causal softmax (rel-shift gather) + P@V
    attn_kernel<<<dim3(QLEN / 128, NZ), 256, ATTN_SMEM>>>(AC, BD, Vb, AV);
    // 7) attn_out = AV @ o_w^T
    gemm_mma_kernel<<<dim3(DM / 128, T_TOK / 128, 1), 256>>>(
        AV, o_w, AO, T_TOK, DM, DM, 0, 0, 0, 0);
    // 8) residual + layernorm -> out
    ln_kernel<<<T_TOK, 256>>>(w, AO, gamma, beta, out);
}

// round 5
// speedup vs baseline: 2.4364x; 1.1263x over previous
#include <cuda_runtime.h>
#include <cuda_bf16.h>

// ---------------- problem dims (fixed) ----------------
#define QLEN 1024
#define BSZ 4
#define DM 1024
#define NH 16
#define DH 64
#define T_TOK 4096
#define NZ 64

// ---------------- scratch (device globals; no cudaMalloc allowed) ----------------
__device__ float g_wheads[(size_t)T_TOK * 3 * DM];
__device__ float g_rkraw [(size_t)T_TOK * DM];
__device__ float g_QW[(size_t)NZ * QLEN * DH];
__device__ float g_QR[(size_t)NZ * QLEN * DH];
__device__ float g_Kb[(size_t)NZ * QLEN * DH];
__device__ float g_Vb[(size_t)NZ * QLEN * DH];
__device__ float g_RK[(size_t)NZ * QLEN * DH];
__device__ float g_AC[(size_t)NZ * QLEN * QLEN + 2048];
__device__ float g_BD[(size_t)NZ * QLEN * QLEN + 2048];
__device__ float g_AV[(size_t)T_TOK * DM];
__device__ float g_AO[(size_t)T_TOK * DM];

// ---------------- tf32 helpers ----------------
__device__ __forceinline__ unsigned f2tf32(float x) {
    unsigned r;
    asm("cvt.rna.tf32.f32 %0, %1;" : "=r"(r) : "f"(x));
    return r;
}

#define MMA_TF32(d0,d1,d2,d3, a0,a1,a2,a3, b0,b1) \
    asm volatile( \
        "mma.sync.aligned.m16n8k8.row.col.f32.tf32.tf32.f32 " \
        "{%0,%1,%2,%3}, {%4,%5,%6,%7}, {%8,%9}, {%0,%1,%2,%3};" \
        : "+f"(d0), "+f"(d1), "+f"(d2), "+f"(d3) \
        : "r"(a0), "r"(a1), "r"(a2), "r"(a3), "r"(b0), "r"(b1))

// ---------------- mma.sync tf32 GEMM: C[M,N] = A[M,K] @ B[N,K]^T ----------------
#define SSTRIDE 36

__global__ void __launch_bounds__(256) gemm_mma_kernel(
    const float* __restrict__ A, const float* __restrict__ B, float* __restrict__ C,
    int M, int N, int K, long long sA, long long sB, long long sC, int tri)
{
    int bx = blockIdx.x, by = blockIdx.y, z = blockIdx.z;
    if (tri == 1 && bx > by) return;
    if (tri == 2 && (bx + by) < (int)gridDim.x - 1) return;

    __shared__ unsigned As[128 * SSTRIDE];
    __shared__ unsigned Bs[128 * SSTRIDE];

    int tid = threadIdx.x;
    int wid = tid >> 5, lane = tid & 31;
    int warp_m = wid & 3;
    int warp_n = wid >> 2;
    int r = lane >> 2, cc = lane & 3;

    const float* Ab = A + (long long)z * sA + (long long)(by * 128) * K;
    const float* Bb = B + (long long)z * sB + (long long)(bx * 128) * K;

    float acc[2][8][4];
#pragma unroll
    for (int mi = 0; mi < 2; mi++)
#pragma unroll
        for (int ni = 0; ni < 8; ni++)
#pragma unroll
            for (int q = 0; q < 4; q++) acc[mi][ni][q] = 0.f;

    for (int k0 = 0; k0 < K; k0 += 32) {
#pragma unroll
        for (int s = tid; s < 1024; s += 256) {
            int row = s >> 3, q = s & 7;
            float4 va = *(const float4*)(Ab + (long long)row * K + k0 + q * 4);
            uint4 ua = make_uint4(f2tf32(va.x), f2tf32(va.y), f2tf32(va.z), f2tf32(va.w));
            *(uint4*)(As + row * SSTRIDE + q * 4) = ua;
            float4 vb = *(const float4*)(Bb + (long long)row * K + k0 + q * 4);
            uint4 ub = make_uint4(f2tf32(vb.x), f2tf32(vb.y), f2tf32(vb.z), f2tf32(vb.w));
            *(uint4*)(Bs + row * SSTRIDE + q * 4) = ub;
        }
        __syncthreads();

#pragma unroll
        for (int ks = 0; ks < 4; ks++) {
            int kb = ks * 8;
            unsigned a[2][4];
#pragma unroll
            for (int mi = 0; mi < 2; mi++) {
                int m0 = warp_m * 32 + mi * 16;
                a[mi][0] = As[(m0 + r)     * SSTRIDE + kb + cc];
                a[mi][1] = As[(m0 + 8 + r) * SSTRIDE + kb + cc];
                a[mi][2] = As[(m0 + r)     * SSTRIDE + kb + cc + 4];
                a[mi][3] = As[(m0 + 8 + r) * SSTRIDE + kb + cc + 4];
            }
#pragma unroll
            for (int ni = 0; ni < 8; ni++) {
                int n0 = warp_n * 64 + ni * 8;
                unsigned b0 = Bs[(n0 + r) * SSTRIDE + kb + cc];
                unsigned b1 = Bs[(n0 + r) * SSTRIDE + kb + cc + 4];
#pragma unroll
                for (int mi = 0; mi < 2; mi++) {
                    MMA_TF32(acc[mi][ni][0], acc[mi][ni][1], acc[mi][ni][2], acc[mi][ni][3],
                             a[mi][0], a[mi][1], a[mi][2], a[mi][3], b0, b1);
                }
            }
        }
        __syncthreads();
    }

    float* Cb = C + (long long)z * sC;
#pragma unroll
    for (int mi = 0; mi < 2; mi++) {
        int m = by * 128 + warp_m * 32 + mi * 16 + r;
#pragma unroll
        for (int ni = 0; ni < 8; ni++) {
            int n = bx * 128 + warp_n * 64 + ni * 8 + cc * 2;
            *(float2*)(Cb + (long long)m * N + n) =
                make_float2(acc[mi][ni][0], acc[mi][ni][1]);
            *(float2*)(Cb + (long long)(m + 8) * N + n) =
                make_float2(acc[mi][ni][2], acc[mi][ni][3]);
        }
    }
}

// ---------------- split heads + biases ----------------
__global__ void __launch_bounds__(256) split_kernel(
    const float* __restrict__ wheads, const float* __restrict__ rkraw,
    const float* __restrict__ rwb, const float* __restrict__ rrb,
    float* __restrict__ QW, float* __restrict__ QR,
    float* __restrict__ Kb, float* __restrict__ Vb, float* __restrict__ RK)
{
    int idx = blockIdx.x * 256 + threadIdx.x;
    int d = idx & 63;
    int i = (idx >> 6) & 1023;
    int z = idx >> 16;
    int b = z >> 4, h = z & 15;
    long long t = (long long)i * BSZ + b;
    int hd = h * 64 + d;
    float q  = wheads[t * 3072 + hd];
    float k  = wheads[t * 3072 + 1024 + hd];
    float v  = wheads[t * 3072 + 2048 + hd];
    float rk = rkraw[t * 1024 + hd];
    QW[idx] = q + rwb[hd];
    QR[idx] = q + rrb[hd];
    Kb[idx] = k;
    Vb[idx] = v;
    RK[idx] = rk;
}

// ---------------- fused causal softmax + tensor-core P@V ----------------
// grid = (8 i-tiles reversed, 64 z), 256 threads = 8 warps (4M x 2N), warp tile 32x32.
// smem: Ps[128][132] (tf32 P, also aliased as V staging), Vs[64][132] (tf32 V^T),
//       alphas[128], lrow[128].
#define PSTR 132
__global__ void __launch_bounds__(256) attn_kernel(
    const float* __restrict__ AC, const float* __restrict__ BD,
    const float* __restrict__ Vb, float* __restrict__ AV)
{
    extern __shared__ float sm[];
    unsigned* Ps = (unsigned*)sm;                       // [128][132]
    float*    Vstage = sm;                              // alias (used before Ps)
    unsigned* Vs = (unsigned*)(sm + 128 * PSTR);        // [64][132]
    float* alphas = sm + 128 * PSTR + 64 * PSTR;        // [128]
    float* lrow   = alphas + 128;                       // [128]

    int it = (int)gridDim.x - 1 - blockIdx.x;           // heavy tiles first
    int z = blockIdx.y;
    int b = z >> 4, h = z & 15;
    const float* ACz = AC + (long long)z * (QLEN * QLEN);
    const float* BDz = BD + (long long)z * (QLEN * QLEN);
    const float* Vz  = Vb + (long long)z * (QLEN * DH);

    int tid = threadIdx.x, tx = tid & 15, ty = tid >> 4;
    int wid = tid >> 5, lane = tid & 31;
    int warp_m = wid & 3, warp_n = wid >> 2;
    int r = lane >> 2, cc = lane & 3;
    int i0 = it << 7;

    float acc[2][4][4];
#pragma unroll
    for (int mi = 0; mi < 2; mi++)
#pragma unroll
        for (int ni = 0; ni < 4; ni++)
#pragma unroll
            for (int q = 0; q < 4; q++) acc[mi][ni][q] = 0.f;

    float m_loc[8], l_loc[8];
#pragma unroll
    for (int u = 0; u < 8; u++) { m_loc[u] = -1e30f; l_loc[u] = 0.f; }

    const float scale = 0.125f;

    for (int jt = 0; jt <= it; jt++) {
        int j0 = jt << 7;

        // ---- V tile: coalesced load into staging (aliases Ps) ----
#pragma unroll
        for (int s2 = tid; s2 < 2048; s2 += 256) {
            int tj = s2 >> 4, dq = s2 & 15;
            *(float4*)(Vstage + tj * 68 + dq * 4) =
                *(const float4*)(Vz + (long long)(j0 + tj) * DH + dq * 4);
        }
        __syncthreads();
        // ---- smem transpose + tf32 round: Vs[d][j] ----
#pragma unroll
        for (int s2 = tid; s2 < 8192; s2 += 256) {
            int d = s2 >> 7, j = s2 & 127;
            Vs[d * PSTR + j] = f2tf32(Vstage[j * 68 + d]);
        }
        __syncthreads();

        // ---- softmax phase (row-owner threads) ----
#pragma unroll
        for (int a = 0; a < 8; a++) {
            int row = ty * 8 + a;
            int i = i0 + row;
            const float* acp = ACz + (long long)i * QLEN + j0 + tx * 8;
            const float* bdp = BDz + (long long)i * QLEN + (j0 + tx * 8 - i + (QLEN - 1));
            float sv[8];
#pragma unroll
            for (int bb = 0; bb < 8; bb++) {
                int j = j0 + tx * 8 + bb;
                sv[bb] = (j <= i) ? (acp[bb] + bdp[bb]) * scale : -1e30f;
            }
            float mx = sv[0];
#pragma unroll
            for (int bb = 1; bb < 8; bb++) mx = fmaxf(mx, sv[bb]);
#pragma unroll
            for (int off = 8; off >= 1; off >>= 1)
                mx = fmaxf(mx, __shfl_xor_sync(0xffffffffu, mx, off, 16));
            float mold = m_loc[a];
            float mnew = fmaxf(mold, mx);
            float al = __expf(mold - mnew);
            float ps = 0.f;
#pragma unroll
            for (int bb = 0; bb < 8; bb++) {
                float p = __expf(sv[bb] - mnew);
                sv[bb] = p; ps += p;
            }
#pragma unroll
            for (int off = 8; off >= 1; off >>= 1)
                ps += __shfl_xor_sync(0xffffffffu, ps, off, 16);
            m_loc[a] = mnew;
            l_loc[a] = l_loc[a] * al + ps;
            if (tx == 0) alphas[row] = al;
            uint4 p0 = make_uint4(f2tf32(sv[0]), f2tf32(sv[1]), f2tf32(sv[2]), f2tf32(sv[3]));
            uint4 p1 = make_uint4(f2tf32(sv[4]), f2tf32(sv[5]), f2tf32(sv[6]), f2tf32(sv[7]));
            *(uint4*)(Ps + row * PSTR + tx * 8) = p0;
            *(uint4*)(Ps + row * PSTR + tx * 8 + 4) = p1;
        }
        __syncthreads();

        // ---- rescale accumulators by alpha[row] ----
#pragma unroll
        for (int mi = 0; mi < 2; mi++) {
            int row0 = warp_m * 32 + mi * 16 + r;
            float al0 = alphas[row0], al1 = alphas[row0 + 8];
#pragma unroll
            for (int ni = 0; ni < 4; ni++) {
                acc[mi][ni][0] *= al0; acc[mi][ni][1] *= al0;
                acc[mi][ni][2] *= al1; acc[mi][ni][3] *= al1;
            }
        }

        // ---- tensor-core P@V: 16 k-steps of m16n8k8 ----
#pragma unroll
        for (int ks = 0; ks < 16; ks++) {
            int kb = ks * 8;
            unsigned a[2][4];
#pragma unroll
            for (int mi = 0; mi < 2; mi++) {
                int m0 = warp_m * 32 + mi * 16;
                a[mi][0] = Ps[(m0 + r)     * PSTR + kb + cc];
                a[mi][1] = Ps[(m0 + 8 + r) * PSTR + kb + cc];
                a[mi][2] = Ps[(m0 + r)     * PSTR + kb + cc + 4];
                a[mi][3] = Ps[(m0 + 8 + r) * PSTR + kb + cc + 4];
            }
#pragma unroll
            for (int ni = 0; ni < 4; ni++) {
                int n0 = warp_n * 32 + ni * 8;
                unsigned b0 = Vs[(n0 + r) * PSTR + kb + cc];
                unsigned b1 = Vs[(n0 + r) * PSTR + kb + cc + 4];
#pragma unroll
                for (int mi = 0; mi < 2; mi++) {
                    MMA_TF32(acc[mi][ni][0], acc[mi][ni][1], acc[mi][ni][2], acc[mi][ni][3],
                             a[mi][0], a[mi][1], a[mi][2], a[mi][3], b0, b1);
                }
            }
        }
        __syncthreads();
    }

    // publish row sums, then normalize + store
#pragma unroll
    for (int a = 0; a < 8; a++)
        if (tx == 0) lrow[ty * 8 + a] = l_loc[a];
    __syncthreads();

#pragma unroll
    for (int mi = 0; mi < 2; mi++) {
        int row0 = warp_m * 32 + mi * 16 + r;
        float inv0 = 1.f / lrow[row0];
        float inv1 = 1.f / lrow[row0 + 8];
        int i_a = i0 + row0;
        int i_b = i_a + 8;
        long long ta = (long long)i_a * BSZ + b;
        long long tb = (long long)i_b * BSZ + b;
#pragma unroll
        for (int ni = 0; ni < 4; ni++) {
            int d = warp_n * 32 + ni * 8 + cc * 2;
            *(float2*)(AV + ta * DM + h * 64 + d) =
                make_float2(acc[mi][ni][0] * inv0, acc[mi][ni][1] * inv0);
            *(float2*)(AV + tb * DM + h * 64 + d) =
                make_float2(acc[mi][ni][2] * inv1, acc[mi][ni][3] * inv1);
        }
    }
}

// ---------------- residual + layernorm ----------------
__global__ void __launch_bounds__(256) ln_kernel(
    const float* __restrict__ w, const float* __restrict__ ao,
    const float* __restrict__ g, const float* __restrict__ be,
    float* __restrict__ out)
{
    long long t = blockIdx.x;
    int tid = threadIdx.x;
    __shared__ float red[8];
    __shared__ float s_mu, s_rstd;

    float4 wx = *(const float4*)(w  + t * DM + tid * 4);
    float4 ax = *(const float4*)(ao + t * DM + tid * 4);
    float x0 = wx.x + ax.x, x1 = wx.y + ax.y, x2 = wx.z + ax.z, x3 = wx.w + ax.w;

    float s = x0 + x1 + x2 + x3;
#pragma unroll
    for (int off = 16; off >= 1; off >>= 1) s += __shfl_xor_sync(0xffffffffu, s, off);
    if ((tid & 31) == 0) red[tid >> 5] = s;
    __syncthreads();
    if (tid == 0) {
        float a = 0;
#pragma unroll
        for (int i2 = 0; i2 < 8; i2++) a += red[i2];
        s_mu = a * (1.f / DM);
    }
    __syncthreads();
    float mu = s_mu;
    float d0 = x0 - mu, d1 = x1 - mu, d2 = x2 - mu, d3 = x3 - mu;
    float v = d0 * d0 + d1 * d1 + d2 * d2 + d3 * d3;
#pragma unroll
    for (int off = 16; off >= 1; off >>= 1) v += __shfl_xor_sync(0xffffffffu, v, off);
    if ((tid & 31) == 0) red[tid >> 5] = v;
    __syncthreads();
    if (tid == 0) {
        float a = 0;
#pragma unroll
        for (int i2 = 0; i2 < 8; i2++) a += red[i2];
        s_rstd = rsqrtf(a * (1.f / DM) + 1e-5f);
    }
    __syncthreads();
    float rs = s_rstd;
    float4 gg = *(const float4*)(g  + tid * 4);
    float4 bb = *(const float4*)(be + tid * 4);
    float4 o = make_float4(d0 * rs * gg.x + bb.x, d1 * rs * gg.y + bb.y,
                           d2 * rs * gg.z + bb.z, d3 * rs * gg.w + bb.w);
    *(float4*)(out + t * DM + tid * 4) = o;
}

// ---------------- host launcher ----------------
extern "C" void kernel_launch(void* const* d_in, const int* in_sizes, int n_in,
                              void* d_out, int out_size)
{
    const float* w       = (const float*)d_in[0];
    const float* r       = (const float*)d_in[1];
    const float* rwb     = (const float*)d_in[2];
    const float* rrb     = (const float*)d_in[3];
    const float* qkv_w   = (const float*)d_in[4];
    const float* r_net_w = (const float*)d_in[5];
    const float* o_w     = (const float*)d_in[6];
    const float* gamma   = (const float*)d_in[7];
    const float* beta    = (const float*)d_in[8];
    float* out = (float*)d_out;

    float *wheads, *rkraw, *QW, *QR, *Kb, *Vb, *RK, *AC, *BD, *AV, *AO;
    cudaGetSymbolAddress((void**)&wheads, g_wheads);
    cudaGetSymbolAddress((void**)&rkraw,  g_rkraw);
    cudaGetSymbolAddress((void**)&QW, g_QW);
    cudaGetSymbolAddress((void**)&QR, g_QR);
    cudaGetSymbolAddress((void**)&Kb, g_Kb);
    cudaGetSymbolAddress((void**)&Vb, g_Vb);
    cudaGetSymbolAddress((void**)&RK, g_RK);
    cudaGetSymbolAddress((void**)&AC, g_AC);
    cudaGetSymbolAddress((void**)&BD, g_BD);
    cudaGetSymbolAddress((void**)&AV, g_AV);
    cudaGetSymbolAddress((void**)&AO, g_AO);

    const int ATTN_SMEM = (128 * PSTR + 64 * PSTR + 256) * 4;   // 102,400 B
    cudaFuncSetAttribute(attn_kernel, cudaFuncAttributeMaxDynamicSharedMemorySize, ATTN_SMEM);

    // 1) w_heads = w @ qkv_w^T   [4096 x 3072]
    gemm_mma_kernel<<<dim3(3072 / 128, T_TOK / 128, 1), 256>>>(
        w, qkv_w, wheads, T_TOK, 3072, DM, 0, 0, 0, 0);
    // 2) r_head_k = r @ r_net_w^T   [4096 x 1024]
    gemm_mma_kernel<<<dim3(DM / 128, T_TOK / 128, 1), 256>>>(
        r, r_net_w, rkraw, T_TOK, DM, DM, 0, 0, 0, 0);
    // 3) split + biases
    split_kernel<<<(NZ * QLEN * DH) / 256, 256>>>(wheads, rkraw, rwb, rrb, QW, QR, Kb, Vb, RK);
    // 4) AC = (q+rwb) . k   batched, lower-triangle tiles
    gemm_mma_kernel<<<dim3(QLEN / 128, QLEN / 128, NZ), 256>>>(
        QW, Kb, AC, QLEN, QLEN, DH,
        (long long)QLEN * DH, (long long)QLEN * DH, (long long)QLEN * QLEN, 1);
    // 5) BD = (q+rrb) . rk   batched, band tiles
    gemm_mma_kernel<<<dim3(QLEN / 128, QLEN / 128, NZ), 256>>>(
        QR, RK, BD, QLEN, QLEN, DH,
        (long long)QLEN * DH, (long long)QLEN * DH, (long long)QLEN * QLEN, 2);
    // 6) causal softmax (rel-shift gather) + tensor-core P@V
    attn_kernel<<<dim3(QLEN / 128, NZ), 256, ATTN_SMEM>>>(AC, BD, Vb, AV);
    // 7) attn_out = AV @ o_w^T
    gemm_mma_kernel<<<dim3(DM / 128, T_TOK / 128, 1), 256>>>(
        AV, o_w, AO, T_TOK, DM, DM, 0, 0, 0, 0);
    // 8) residual + layernorm -> out
    ln_kernel<<<T_TOK, 256>>>(w, AO, gamma, beta, out);
}

// round 6
// speedup vs baseline: 2.6666x; 1.0945x over previous
#include <cuda_runtime.h>
#include <cuda_bf16.h>

// ---------------- problem dims (fixed) ----------------
#define QLEN 1024
#define BSZ 4
#define DM 1024
#define NH 16
#define DH 64
#define T_TOK 4096
#define NZ 64

// ---------------- scratch (device globals; no cudaMalloc allowed) ----------------
__device__ float g_wheads[(size_t)T_TOK * 3 * DM];
__device__ float g_rkraw [(size_t)T_TOK * DM];
__device__ float g_QW[(size_t)NZ * QLEN * DH];
__device__ float g_QR[(size_t)NZ * QLEN * DH];
__device__ float g_Kb[(size_t)NZ * QLEN * DH];
__device__ float g_Vb[(size_t)NZ * QLEN * DH];
__device__ float g_RK[(size_t)NZ * QLEN * DH];
__device__ float g_AC[(size_t)NZ * QLEN * QLEN + 2048];
__device__ float g_BD[(size_t)NZ * QLEN * QLEN + 2048];
__device__ float g_AV[(size_t)T_TOK * DM];
__device__ float g_AO[(size_t)T_TOK * DM];

#define MMA_TF32(d0,d1,d2,d3, a0,a1,a2,a3, b0,b1) \
    asm volatile( \
        "mma.sync.aligned.m16n8k8.row.col.f32.tf32.tf32.f32 " \
        "{%0,%1,%2,%3}, {%4,%5,%6,%7}, {%8,%9}, {%0,%1,%2,%3};" \
        : "+f"(d0), "+f"(d1), "+f"(d2), "+f"(d3) \
        : "r"(a0), "r"(a1), "r"(a2), "r"(a3), "r"(b0), "r"(b1))

#define CP16(dst_u32, src_ptr) \
    asm volatile("cp.async.cg.shared.global [%0], [%1], 16;" \
                 :: "r"(dst_u32), "l"(src_ptr))
#define CP_COMMIT() asm volatile("cp.async.commit_group;")
#define CP_WAIT(n)  asm volatile("cp.async.wait_group %0;" :: "n"(n))

// ---------------- mma.sync tf32 GEMM, cp.async double-buffered ----------------
// C[M,N] = A[M,K] @ B[N,K]^T. 128x128 CTA tile, BK=32, 8 warps (4M x 2N).
// Raw fp32 bits fed to tf32 MMA (hw truncates low mantissa).
// tri=1: skip bx>by. tri=2: skip bx+by<gridDim.x-1.
#define SSTRIDE 36
// byte sizes: one operand buffer = 128*36*4 = 18432 B; A:2 bufs, B:2 bufs
#define GEMM_SMEM (4 * 18432)

__global__ void __launch_bounds__(256) gemm_mma_kernel(
    const float* __restrict__ A, const float* __restrict__ B, float* __restrict__ C,
    int M, int N, int K, long long sA, long long sB, long long sC, int tri)
{
    int bx = blockIdx.x, by = blockIdx.y, z = blockIdx.z;
    if (tri == 1 && bx > by) return;
    if (tri == 2 && (bx + by) < (int)gridDim.x - 1) return;

    extern __shared__ float smp[];
    unsigned sbase = (unsigned)__cvta_generic_to_shared(smp);

    int tid = threadIdx.x;
    int wid = tid >> 5, lane = tid & 31;
    int warp_m = wid & 3, warp_n = wid >> 2;
    int r = lane >> 2, cc = lane & 3;

    const float* Ab = A + (long long)z * sA + (long long)(by * 128) * K;
    const float* Bb = B + (long long)z * sB + (long long)(bx * 128) * K;

    float acc[2][8][4];
#pragma unroll
    for (int mi = 0; mi < 2; mi++)
#pragma unroll
        for (int ni = 0; ni < 8; ni++)
#pragma unroll
            for (int q = 0; q < 4; q++) acc[mi][ni][q] = 0.f;

    int nch = K >> 5;

    // prologue: chunk 0 into buf 0
    {
        unsigned ad = sbase, bd = sbase + 36864u;
#pragma unroll
        for (int s = tid; s < 1024; s += 256) {
            int row = s >> 3, q = s & 7;
            unsigned off = (unsigned)(row * SSTRIDE + q * 4) * 4u;
            CP16(ad + off, Ab + (long long)row * K + q * 4);
            CP16(bd + off, Bb + (long long)row * K + q * 4);
        }
        CP_COMMIT();
    }

    for (int c = 0; c < nch; c++) {
        if (c + 1 < nch) {
            int k0 = (c + 1) << 5;
            int buf = (c + 1) & 1;
            unsigned ad = sbase + (unsigned)buf * 18432u;
            unsigned bd = sbase + 36864u + (unsigned)buf * 18432u;
#pragma unroll
            for (int s = tid; s < 1024; s += 256) {
                int row = s >> 3, q = s & 7;
                unsigned off = (unsigned)(row * SSTRIDE + q * 4) * 4u;
                CP16(ad + off, Ab + (long long)row * K + k0 + q * 4);
                CP16(bd + off, Bb + (long long)row * K + k0 + q * 4);
            }
            CP_COMMIT();
            CP_WAIT(1);
        } else {
            CP_WAIT(0);
        }
        __syncthreads();

        const unsigned* As = (const unsigned*)(smp + (c & 1) * 4608);
        const unsigned* Bs = (const unsigned*)(smp + 9216 + (c & 1) * 4608);

#pragma unroll
        for (int ks = 0; ks < 4; ks++) {
            int kb = ks * 8;
            unsigned a[2][4];
#pragma unroll
            for (int mi = 0; mi < 2; mi++) {
                int m0 = warp_m * 32 + mi * 16;
                a[mi][0] = As[(m0 + r)     * SSTRIDE + kb + cc];
                a[mi][1] = As[(m0 + 8 + r) * SSTRIDE + kb + cc];
                a[mi][2] = As[(m0 + r)     * SSTRIDE + kb + cc + 4];
                a[mi][3] = As[(m0 + 8 + r) * SSTRIDE + kb + cc + 4];
            }
#pragma unroll
            for (int ni = 0; ni < 8; ni++) {
                int n0 = warp_n * 64 + ni * 8;
                unsigned b0 = Bs[(n0 + r) * SSTRIDE + kb + cc];
                unsigned b1 = Bs[(n0 + r) * SSTRIDE + kb + cc + 4];
#pragma unroll
                for (int mi = 0; mi < 2; mi++) {
                    MMA_TF32(acc[mi][ni][0], acc[mi][ni][1], acc[mi][ni][2], acc[mi][ni][3],
                             a[mi][0], a[mi][1], a[mi][2], a[mi][3], b0, b1);
                }
            }
        }
        __syncthreads();
    }

    float* Cb = C + (long long)z * sC;
#pragma unroll
    for (int mi = 0; mi < 2; mi++) {
        int m = by * 128 + warp_m * 32 + mi * 16 + r;
#pragma unroll
        for (int ni = 0; ni < 8; ni++) {
            int n = bx * 128 + warp_n * 64 + ni * 8 + cc * 2;
            *(float2*)(Cb + (long long)m * N + n) =
                make_float2(acc[mi][ni][0], acc[mi][ni][1]);
            *(float2*)(Cb + (long long)(m + 8) * N + n) =
                make_float2(acc[mi][ni][2], acc[mi][ni][3]);
        }
    }
}

// ---------------- split heads + biases ----------------
__global__ void __launch_bounds__(256) split_kernel(
    const float* __restrict__ wheads, const float* __restrict__ rkraw,
    const float* __restrict__ rwb, const float* __restrict__ rrb,
    float* __restrict__ QW, float* __restrict__ QR,
    float* __restrict__ Kb, float* __restrict__ Vb, float* __restrict__ RK)
{
    int idx = blockIdx.x * 256 + threadIdx.x;
    int d = idx & 63;
    int i = (idx >> 6) & 1023;
    int z = idx >> 16;
    int b = z >> 4, h = z & 15;
    long long t = (long long)i * BSZ + b;
    int hd = h * 64 + d;
    float q  = wheads[t * 3072 + hd];
    float k  = wheads[t * 3072 + 1024 + hd];
    float v  = wheads[t * 3072 + 2048 + hd];
    float rk = rkraw[t * 1024 + hd];
    QW[idx] = q + rwb[hd];
    QR[idx] = q + rrb[hd];
    Kb[idx] = k;
    Vb[idx] = v;
    RK[idx] = rk;
}

// ---------------- fused causal softmax + tensor-core P@V ----------------
// grid = (8 i-tiles reversed, 64 z), 256 threads = 8 warps (4M x 2N), warp tile 32x32.
// V cp.async overlapped under the softmax phase.
#define PSTR 132
#define ATTN_SMEM ((128 * PSTR + 64 * PSTR + 128 * 68 + 256) * 4)

__global__ void __launch_bounds__(256) attn_kernel(
    const float* __restrict__ AC, const float* __restrict__ BD,
    const float* __restrict__ Vb, float* __restrict__ AV)
{
    extern __shared__ float sm[];
    float* Ps     = sm;                                  // [128][132]
    float* Vs     = sm + 128 * PSTR;                     // [64][132]
    float* Vstage = sm + 128 * PSTR + 64 * PSTR;         // [128][68]
    float* alphas = Vstage + 128 * 68;                   // [128]
    float* lrow   = alphas + 128;                        // [128]
    unsigned vst = (unsigned)__cvta_generic_to_shared(Vstage);

    int it = (int)gridDim.x - 1 - blockIdx.x;            // heavy tiles first
    int z = blockIdx.y;
    int b = z >> 4, h = z & 15;
    const float* ACz = AC + (long long)z * (QLEN * QLEN);
    const float* BDz = BD + (long long)z * (QLEN * QLEN);
    const float* Vz  = Vb + (long long)z * (QLEN * DH);

    int tid = threadIdx.x, tx = tid & 15, ty = tid >> 4;
    int wid = tid >> 5, lane = tid & 31;
    int warp_m = wid & 3, warp_n = wid >> 2;
    int r = lane >> 2, cc = lane & 3;
    int i0 = it << 7;

    float acc[2][4][4];
#pragma unroll
    for (int mi = 0; mi < 2; mi++)
#pragma unroll
        for (int ni = 0; ni < 4; ni++)
#pragma unroll
            for (int q = 0; q < 4; q++) acc[mi][ni][q] = 0.f;

    float m_loc[8], l_loc[8];
#pragma unroll
    for (int u = 0; u < 8; u++) { m_loc[u] = -1e30f; l_loc[u] = 0.f; }

    const float scale = 0.125f;

    for (int jt = 0; jt <= it; jt++) {
        int j0 = jt << 7;

        // ---- (1) issue V tile cp.async (lands under softmax) ----
#pragma unroll
        for (int s2 = tid; s2 < 2048; s2 += 256) {
            int tj = s2 >> 4, dq = s2 & 15;
            CP16(vst + (unsigned)(tj * 68 + dq * 4) * 4u,
                 Vz + (long long)(j0 + tj) * DH + dq * 4);
        }
        CP_COMMIT();

        // ---- (2) softmax phase (reads AC/BD from global) ----
#pragma unroll
        for (int a = 0; a < 8; a++) {
            int row = ty * 8 + a;
            int i = i0 + row;
            const float* acp = ACz + (long long)i * QLEN + j0 + tx * 8;
            const float* bdp = BDz + (long long)i * QLEN + (j0 + tx * 8 - i + (QLEN - 1));
            float sv[8];
#pragma unroll
            for (int bb = 0; bb < 8; bb++) {
                int j = j0 + tx * 8 + bb;
                sv[bb] = (j <= i) ? (acp[bb] + bdp[bb]) * scale : -1e30f;
            }
            float mx = sv[0];
#pragma unroll
            for (int bb = 1; bb < 8; bb++) mx = fmaxf(mx, sv[bb]);
#pragma unroll
            for (int off = 8; off >= 1; off >>= 1)
                mx = fmaxf(mx, __shfl_xor_sync(0xffffffffu, mx, off, 16));
            float mold = m_loc[a];
            float mnew = fmaxf(mold, mx);
            float al = __expf(mold - mnew);
            float ps = 0.f;
#pragma unroll
            for (int bb = 0; bb < 8; bb++) {
                float p = __expf(sv[bb] - mnew);
                sv[bb] = p; ps += p;
            }
#pragma unroll
            for (int off = 8; off >= 1; off >>= 1)
                ps += __shfl_xor_sync(0xffffffffu, ps, off, 16);
            m_loc[a] = mnew;
            l_loc[a] = l_loc[a] * al + ps;
            if (tx == 0) alphas[row] = al;
            *(float4*)(Ps + row * PSTR + tx * 8) =
                make_float4(sv[0], sv[1], sv[2], sv[3]);
            *(float4*)(Ps + row * PSTR + tx * 8 + 4) =
                make_float4(sv[4], sv[5], sv[6], sv[7]);
        }

        // ---- (3) V arrival + (4) transpose (raw bits as tf32) ----
        CP_WAIT(0);
        __syncthreads();
#pragma unroll
        for (int s2 = tid; s2 < 8192; s2 += 256) {
            int d = s2 >> 7, j = s2 & 127;
            Vs[d * PSTR + j] = Vstage[j * 68 + d];
        }
        __syncthreads();

        // ---- (5) rescale + tensor-core P@V ----
#pragma unroll
        for (int mi = 0; mi < 2; mi++) {
            int row0 = warp_m * 32 + mi * 16 + r;
            float al0 = alphas[row0], al1 = alphas[row0 + 8];
#pragma unroll
            for (int ni = 0; ni < 4; ni++) {
                acc[mi][ni][0] *= al0; acc[mi][ni][1] *= al0;
                acc[mi][ni][2] *= al1; acc[mi][ni][3] *= al1;
            }
        }

        const unsigned* Pu = (const unsigned*)Ps;
        const unsigned* Vu = (const unsigned*)Vs;
#pragma unroll
        for (int ks = 0; ks < 16; ks++) {
            int kb = ks * 8;
            unsigned a[2][4];
#pragma unroll
            for (int mi = 0; mi < 2; mi++) {
                int m0 = warp_m * 32 + mi * 16;
                a[mi][0] = Pu[(m0 + r)     * PSTR + kb + cc];
                a[mi][1] = Pu[(m0 + 8 + r) * PSTR + kb + cc];
                a[mi][2] = Pu[(m0 + r)     * PSTR + kb + cc + 4];
                a[mi][3] = Pu[(m0 + 8 + r) * PSTR + kb + cc + 4];
            }
#pragma unroll
            for (int ni = 0; ni < 4; ni++) {
                int n0 = warp_n * 32 + ni * 8;
                unsigned b0 = Vu[(n0 + r) * PSTR + kb + cc];
                unsigned b1 = Vu[(n0 + r) * PSTR + kb + cc + 4];
#pragma unroll
                for (int mi = 0; mi < 2; mi++) {
                    MMA_TF32(acc[mi][ni][0], acc[mi][ni][1], acc[mi][ni][2], acc[mi][ni][3],
                             a[mi][0], a[mi][1], a[mi][2], a[mi][3], b0, b1);
                }
            }
        }
        __syncthreads();
    }

    // publish row sums, then normalize + store
#pragma unroll
    for (int a = 0; a < 8; a++)
        if (tx == 0) lrow[ty * 8 + a] = l_loc[a];
    __syncthreads();

#pragma unroll
    for (int mi = 0; mi < 2; mi++) {
        int row0 = warp_m * 32 + mi * 16 + r;
        float inv0 = 1.f / lrow[row0];
        float inv1 = 1.f / lrow[row0 + 8];
        int i_a = i0 + row0;
        int i_b = i_a + 8;
        long long ta = (long long)i_a * BSZ + b;
        long long tb = (long long)i_b * BSZ + b;
#pragma unroll
        for (int ni = 0; ni < 4; ni++) {
            int d = warp_n * 32 + ni * 8 + cc * 2;
            *(float2*)(AV + ta * DM + h * 64 + d) =
                make_float2(acc[mi][ni][0] * inv0, acc[mi][ni][1] * inv0);
            *(float2*)(AV + tb * DM + h * 64 + d) =
                make_float2(acc[mi][ni][2] * inv1, acc[mi][ni][3] * inv1);
        }
    }
}

// ---------------- residual + layernorm ----------------
__global__ void __launch_bounds__(256) ln_kernel(
    const float* __restrict__ w, const float* __restrict__ ao,
    const float* __restrict__ g, const float* __restrict__ be,
    float* __restrict__ out)
{
    long long t = blockIdx.x;
    int tid = threadIdx.x;
    __shared__ float red[8];
    __shared__ float s_mu, s_rstd;

    float4 wx = *(const float4*)(w  + t * DM + tid * 4);
    float4 ax = *(const float4*)(ao + t * DM + tid * 4);
    float x0 = wx.x + ax.x, x1 = wx.y + ax.y, x2 = wx.z + ax.z, x3 = wx.w + ax.w;

    float s = x0 + x1 + x2 + x3;
#pragma unroll
    for (int off = 16; off >= 1; off >>= 1) s += __shfl_xor_sync(0xffffffffu, s, off);
    if ((tid & 31) == 0) red[tid >> 5] = s;
    __syncthreads();
    if (tid == 0) {
        float a = 0;
#pragma unroll
        for (int i2 = 0; i2 < 8; i2++) a += red[i2];
        s_mu = a * (1.f / DM);
    }
    __syncthreads();
    float mu = s_mu;
    float d0 = x0 - mu, d1 = x1 - mu, d2 = x2 - mu, d3 = x3 - mu;
    float v = d0 * d0 + d1 * d1 + d2 * d2 + d3 * d3;
#pragma unroll
    for (int off = 16; off >= 1; off >>= 1) v += __shfl_xor_sync(0xffffffffu, v, off);
    if ((tid & 31) == 0) red[tid >> 5] = v;
    __syncthreads();
    if (tid == 0) {
        float a = 0;
#pragma unroll
        for (int i2 = 0; i2 < 8; i2++) a += red[i2];
        s_rstd = rsqrtf(a * (1.f / DM) + 1e-5f);
    }
    __syncthreads();
    float rs = s_rstd;
    float4 gg = *(const float4*)(g  + tid * 4);
    float4 bb = *(const float4*)(be + tid * 4);
    float4 o = make_float4(d0 * rs * gg.x + bb.x, d1 * rs * gg.y + bb.y,
                           d2 * rs * gg.z + bb.z, d3 * rs * gg.w + bb.w);
    *(float4*)(out + t * DM + tid * 4) = o;
}

// ---------------- host launcher ----------------
extern "C" void kernel_launch(void* const* d_in, const int* in_sizes, int n_in,
                              void* d_out, int out_size)
{
    const float* w       = (const float*)d_in[0];
    const float* r       = (const float*)d_in[1];
    const float* rwb     = (const float*)d_in[2];
    const float* rrb     = (const float*)d_in[3];
    const float* qkv_w   = (const float*)d_in[4];
    const float* r_net_w = (const float*)d_in[5];
    const float* o_w     = (const float*)d_in[6];
    const float* gamma   = (const float*)d_in[7];
    const float* beta    = (const float*)d_in[8];
    float* out = (float*)d_out;

    float *wheads, *rkraw, *QW, *QR, *Kb, *Vb, *RK, *AC, *BD, *AV, *AO;
    cudaGetSymbolAddress((void**)&wheads, g_wheads);
    cudaGetSymbolAddress((void**)&rkraw,  g_rkraw);
    cudaGetSymbolAddress((void**)&QW, g_QW);
    cudaGetSymbolAddress((void**)&QR, g_QR);
    cudaGetSymbolAddress((void**)&Kb, g_Kb);
    cudaGetSymbolAddress((void**)&Vb, g_Vb);
    cudaGetSymbolAddress((void**)&RK, g_RK);
    cudaGetSymbolAddress((void**)&AC, g_AC);
    cudaGetSymbolAddress((void**)&BD, g_BD);
    cudaGetSymbolAddress((void**)&AV, g_AV);
    cudaGetSymbolAddress((void**)&AO, g_AO);

    cudaFuncSetAttribute(gemm_mma_kernel, cudaFuncAttributeMaxDynamicSharedMemorySize, GEMM_SMEM);
    cudaFuncSetAttribute(attn_kernel, cudaFuncAttributeMaxDynamicSharedMemorySize, ATTN_SMEM);

    // 1) w_heads = w @ qkv_w^T   [4096 x 3072]
    gemm_mma_kernel<<<dim3(3072 / 128, T_TOK / 128, 1), 256, GEMM_SMEM>>>(
        w, qkv_w, wheads, T_TOK, 3072, DM, 0, 0, 0, 0);
    // 2) r_head_k = r @ r_net_w^T   [4096 x 1024]
    gemm_mma_kernel<<<dim3(DM / 128, T_TOK / 128, 1), 256, GEMM_SMEM>>>(
        r, r_net_w, rkraw, T_TOK, DM, DM, 0, 0, 0, 0);
    // 3) split + biases
    split_kernel<<<(NZ * QLEN * DH) / 256, 256>>>(wheads, rkraw, rwb, rrb, QW, QR, Kb, Vb, RK);
    // 4) AC = (q+rwb) . k   batched, lower-triangle tiles
    gemm_mma_kernel<<<dim3(QLEN / 128, QLEN / 128, NZ), 256, GEMM_SMEM>>>(
        QW, Kb, AC, QLEN, QLEN, DH,
        (long long)QLEN * DH, (long long)QLEN * DH, (long long)QLEN * QLEN, 1);
    // 5) BD = (q+rrb) . rk   batched, band tiles
    gemm_mma_kernel<<<dim3(QLEN / 128, QLEN / 128, NZ), 256, GEMM_SMEM>>>(
        QR, RK, BD, QLEN, QLEN, DH,
        (long long)QLEN * DH, (long long)QLEN * DH, (long long)QLEN * QLEN, 2);
    // 6) causal softmax (rel-shift gather) + tensor-core P@V
    attn_kernel<<<dim3(QLEN / 128, NZ), 256, ATTN_SMEM>>>(AC, BD, Vb, AV);
    // 7) attn_out = AV @ o_w^T
    gemm_mma_kernel<<<dim3(DM / 128, T_TOK / 128, 1), 256, GEMM_SMEM>>>(
        AV, o_w, AO, T_TOK, DM, DM, 0, 0, 0, 0);
    // 8) residual + layernorm -> out
    ln_kernel<<<T_TOK, 256>>>(w, AO, gamma, beta, out);
}

// round 9
// speedup vs baseline: 3.0686x; 1.1508x over previous
#include <cuda_runtime.h>
#include <cuda_bf16.h>

// ---------------- problem dims (fixed) ----------------
#define QLEN 1024
#define BSZ 4
#define DM 1024
#define NH 16
#define DH 64
#define T_TOK 4096
#define NZ 64

// ---------------- scratch (device globals; no cudaMalloc allowed) ----------------
__device__ float g_wheads[(size_t)T_TOK * 3 * DM];
__device__ float g_rkraw [(size_t)T_TOK * DM];
__device__ float g_QW[(size_t)NZ * QLEN * DH];
__device__ float g_QR[(size_t)NZ * QLEN * DH];
__device__ float g_Kb[(size_t)NZ * QLEN * DH];
__device__ float g_Vb[(size_t)NZ * QLEN * DH];
__device__ float g_RK[(size_t)NZ * QLEN * DH];
__device__ float g_BD[(size_t)NZ * QLEN * QLEN + 2048];
__device__ float g_AV[(size_t)T_TOK * DM];
__device__ float g_AO[(size_t)T_TOK * DM];

__device__ __forceinline__ unsigned f2tf32(float x) {
    unsigned r;
    asm("cvt.rna.tf32.f32 %0, %1;" : "=r"(r) : "f"(x));
    return r;
}

#define MMA_TF32(d0,d1,d2,d3, a0,a1,a2,a3, b0,b1) \
    asm volatile( \
        "mma.sync.aligned.m16n8k8.row.col.f32.tf32.tf32.f32 " \
        "{%0,%1,%2,%3}, {%4,%5,%6,%7}, {%8,%9}, {%0,%1,%2,%3};" \
        : "+f"(d0), "+f"(d1), "+f"(d2), "+f"(d3) \
        : "r"(a0), "r"(a1), "r"(a2), "r"(a3), "r"(b0), "r"(b1))

#define CP16(dst_u32, src_ptr) \
    asm volatile("cp.async.cg.shared.global [%0], [%1], 16;" \
                 :: "r"(dst_u32), "l"(src_ptr))
#define CP4(dst_u32, src_ptr) \
    asm volatile("cp.async.ca.shared.global [%0], [%1], 4;" \
                 :: "r"(dst_u32), "l"(src_ptr))
#define CP_COMMIT() asm volatile("cp.async.commit_group;")
#define CP_WAIT(n)  asm volatile("cp.async.wait_group %0;" :: "n"(n))

// ---------------- mma.sync tf32 GEMM, cp.async double-buffered ----------------
// C[M,N] = A[M,K] @ B[N,K]^T. 128x128 CTA tile, BK=32, 8 warps (4M x 2N).
// Fragments get +0x1000 rounding bias (emulates RNA before hw tf32 truncation).
// tri=2: skip bx+by<gridDim.x-1 (BD band).
#define SSTRIDE 36
#define GEMM_SMEM (4 * 18432)

__global__ void __launch_bounds__(256) gemm_mma_kernel(
    const float* __restrict__ A, const float* __restrict__ B, float* __restrict__ C,
    int M, int N, int K, long long sA, long long sB, long long sC, int tri)
{
    int bx = blockIdx.x, by = blockIdx.y, z = blockIdx.z;
    if (tri == 2 && (bx + by) < (int)gridDim.x - 1) return;

    extern __shared__ float smp[];
    unsigned sbase = (unsigned)__cvta_generic_to_shared(smp);

    int tid = threadIdx.x;
    int wid = tid >> 5, lane = tid & 31;
    int warp_m = wid & 3, warp_n = wid >> 2;
    int r = lane >> 2, cc = lane & 3;

    const float* Ab = A + (long long)z * sA + (long long)(by * 128) * K;
    const float* Bb = B + (long long)z * sB + (long long)(bx * 128) * K;

    float acc[2][8][4];
#pragma unroll
    for (int mi = 0; mi < 2; mi++)
#pragma unroll
        for (int ni = 0; ni < 8; ni++)
#pragma unroll
            for (int q = 0; q < 4; q++) acc[mi][ni][q] = 0.f;

    int nch = K >> 5;

    {
        unsigned ad = sbase, bd = sbase + 36864u;
#pragma unroll
        for (int s = tid; s < 1024; s += 256) {
            int row = s >> 3, q = s & 7;
            unsigned off = (unsigned)(row * SSTRIDE + q * 4) * 4u;
            CP16(ad + off, Ab + (long long)row * K + q * 4);
            CP16(bd + off, Bb + (long long)row * K + q * 4);
        }
        CP_COMMIT();
    }

    for (int c = 0; c < nch; c++) {
        if (c + 1 < nch) {
            int k0 = (c + 1) << 5;
            int buf = (c + 1) & 1;
            unsigned ad = sbase + (unsigned)buf * 18432u;
            unsigned bd = sbase + 36864u + (unsigned)buf * 18432u;
#pragma unroll
            for (int s = tid; s < 1024; s += 256) {
                int row = s >> 3, q = s & 7;
                unsigned off = (unsigned)(row * SSTRIDE + q * 4) * 4u;
                CP16(ad + off, Ab + (long long)row * K + k0 + q * 4);
                CP16(bd + off, Bb + (long long)row * K + k0 + q * 4);
            }
            CP_COMMIT();
            CP_WAIT(1);
        } else {
            CP_WAIT(0);
        }
        __syncthreads();

        const unsigned* As = (const unsigned*)(smp + (c & 1) * 4608);
        const unsigned* Bs = (const unsigned*)(smp + 9216 + (c & 1) * 4608);

#pragma unroll
        for (int ks = 0; ks < 4; ks++) {
            int kb = ks * 8;
            unsigned a[2][4];
#pragma unroll
            for (int mi = 0; mi < 2; mi++) {
                int m0 = warp_m * 32 + mi * 16;
                a[mi][0] = As[(m0 + r)     * SSTRIDE + kb + cc] + 0x1000u;
                a[mi][1] = As[(m0 + 8 + r) * SSTRIDE + kb + cc] + 0x1000u;
                a[mi][2] = As[(m0 + r)     * SSTRIDE + kb + cc + 4] + 0x1000u;
                a[mi][3] = As[(m0 + 8 + r) * SSTRIDE + kb + cc + 4] + 0x1000u;
            }
#pragma unroll
            for (int ni = 0; ni < 8; ni++) {
                int n0 = warp_n * 64 + ni * 8;
                unsigned b0 = Bs[(n0 + r) * SSTRIDE + kb + cc] + 0x1000u;
                unsigned b1 = Bs[(n0 + r) * SSTRIDE + kb + cc + 4] + 0x1000u;
#pragma unroll
                for (int mi = 0; mi < 2; mi++) {
                    MMA_TF32(acc[mi][ni][0], acc[mi][ni][1], acc[mi][ni][2], acc[mi][ni][3],
                             a[mi][0], a[mi][1], a[mi][2], a[mi][3], b0, b1);
                }
            }
        }
        __syncthreads();
    }

    float* Cb = C + (long long)z * sC;
#pragma unroll
    for (int mi = 0; mi < 2; mi++) {
        int m = by * 128 + warp_m * 32 + mi * 16 + r;
#pragma unroll
        for (int ni = 0; ni < 8; ni++) {
            int n = bx * 128 + warp_n * 64 + ni * 8 + cc * 2;
            *(float2*)(Cb + (long long)m * N + n) =
                make_float2(acc[mi][ni][0], acc[mi][ni][1]);
            *(float2*)(Cb + (long long)(m + 8) * N + n) =
                make_float2(acc[mi][ni][2], acc[mi][ni][3]);
        }
    }
}

// ---------------- split heads + biases (pre-rounded to tf32 via RNA) ----------------
__global__ void __launch_bounds__(256) split_kernel(
    const float* __restrict__ wheads, const float* __restrict__ rkraw,
    const float* __restrict__ rwb, const float* __restrict__ rrb,
    float* __restrict__ QW, float* __restrict__ QR,
    float* __restrict__ Kb, float* __restrict__ Vb, float* __restrict__ RK)
{
    int idx = blockIdx.x * 256 + threadIdx.x;
    int d = idx & 63;
    int i = (idx >> 6) & 1023;
    int z = idx >> 16;
    int b = z >> 4, h = z & 15;
    long long t = (long long)i * BSZ + b;
    int hd = h * 64 + d;
    float q  = wheads[t * 3072 + hd];
    float k  = wheads[t * 3072 + 1024 + hd];
    float v  = wheads[t * 3072 + 2048 + hd];
    float rk = rkraw[t * 1024 + hd];
    QW[idx] = __uint_as_float(f2tf32(q + rwb[hd]));
    QR[idx] = __uint_as_float(f2tf32(q + rrb[hd]));
    Kb[idx] = __uint_as_float(f2tf32(k));
    Vb[idx] = __uint_as_float(f2tf32(v));
    RK[idx] = __uint_as_float(f2tf32(rk));
}

// ---------------- semi-fused attention ----------------
// Per CTA (i-tile it, z): AC computed in-kernel on MMA (QW persistent, K streamed),
// BD added from global (precomputed band GEMM), softmax on fragments, PV on MMA.
// 256 threads = 8 warps, warp tile = 16 rows x full width.
#define QK_STR 68
#define VP_STR 132
// floats: QWs 128*68=8704, Ks 8704, Vs 64*132=8448, Ps 128*132=16896
#define ATTN_QWS 0
#define ATTN_KS  8704
#define ATTN_VS  17408
#define ATTN_PS  25856
#define ATTN_SMEM ((25856 + 16896) * 4)

__global__ void __launch_bounds__(256) attn_kernel(
    const float* __restrict__ BD, const float* __restrict__ Kb,
    const float* __restrict__ Vb, const float* __restrict__ QW,
    float* __restrict__ AV)
{
    extern __shared__ float sm[];
    float* QWs = sm + ATTN_QWS;
    float* Ks  = sm + ATTN_KS;
    float* Vs  = sm + ATTN_VS;
    unsigned* Ps = (unsigned*)(sm + ATTN_PS);
    unsigned qws_a = (unsigned)__cvta_generic_to_shared(QWs);
    unsigned ks_a  = (unsigned)__cvta_generic_to_shared(Ks);
    unsigned vs_a  = (unsigned)__cvta_generic_to_shared(Vs);

    int it = (int)gridDim.x - 1 - blockIdx.x;     // heavy tiles first
    int z = blockIdx.y;
    int b = z >> 4, h = z & 15;
    const float* Kz  = Kb + (long long)z * (QLEN * DH);
    const float* Vz  = Vb + (long long)z * (QLEN * DH);
    const float* QWz = QW + (long long)z * (QLEN * DH);
    const float* BDz = BD + (long long)z * (QLEN * QLEN);

    int tid = threadIdx.x;
    int wid = tid >> 5, lane = tid & 31;
    int r = lane >> 2, cc = lane & 3;
    int i0 = it << 7;
    int rowA = wid * 16 + r;          // warp's rows: rowA, rowA+8
    int iA = i0 + rowA, iB = iA + 8;

    // O accumulators: 16 x 64 per warp -> ni 0..7
    float oacc[8][4];
#pragma unroll
    for (int ni = 0; ni < 8; ni++)
#pragma unroll
        for (int q = 0; q < 4; q++) oacc[ni][q] = 0.f;

    float mA = -1e30f, mB = -1e30f, lA = 0.f, lB = 0.f;

    // prologue: QW tile + K(0)   (group 1)
#pragma unroll
    for (int s = tid; s < 2048; s += 256) {
        int row = s >> 4, q = s & 15;
        CP16(qws_a + (unsigned)(row * QK_STR + q * 4) * 4u,
             QWz + (long long)(i0 + row) * DH + q * 4);
        CP16(ks_a + (unsigned)(row * QK_STR + q * 4) * 4u,
             Kz + (long long)row * DH + q * 4);
    }
    CP_COMMIT();

    for (int jt = 0; jt <= it; jt++) {
        int j0 = jt << 7;

        // [a] V(jt): transposed 4B cp.async (coalesced global)   (group)
#pragma unroll
        for (int s = tid; s < 8192; s += 256) {
            int d = s & 63, j = s >> 6;
            CP4(vs_a + (unsigned)(d * VP_STR + j) * 4u,
                Vz + (long long)(j0 + j) * DH + d);
        }
        CP_COMMIT();

        // [b] wait K(jt), AC MMA -> S fragments
        CP_WAIT(1);
        __syncthreads();

        float s_fr[16][4];
#pragma unroll
        for (int ni = 0; ni < 16; ni++)
#pragma unroll
            for (int q = 0; q < 4; q++) s_fr[ni][q] = 0.f;

        {
            const unsigned* Qu = (const unsigned*)QWs;
            const unsigned* Ku = (const unsigned*)Ks;
            int m0 = wid * 16;
#pragma unroll
            for (int ks = 0; ks < 8; ks++) {
                int kb = ks * 8;
                unsigned a0 = Qu[(m0 + r)     * QK_STR + kb + cc];
                unsigned a1 = Qu[(m0 + 8 + r) * QK_STR + kb + cc];
                unsigned a2 = Qu[(m0 + r)     * QK_STR + kb + cc + 4];
                unsigned a3 = Qu[(m0 + 8 + r) * QK_STR + kb + cc + 4];
#pragma unroll
                for (int ni = 0; ni < 16; ni++) {
                    unsigned b0 = Ku[(ni * 8 + r) * QK_STR + kb + cc];
                    unsigned b1 = Ku[(ni * 8 + r) * QK_STR + kb + cc + 4];
                    MMA_TF32(s_fr[ni][0], s_fr[ni][1], s_fr[ni][2], s_fr[ni][3],
                             a0, a1, a2, a3, b0, b1);
                }
            }
        }
        __syncthreads();   // Ks consumed

        // [c] prefetch K(jt+1)   (group; skip on last iter)
        if (jt < it) {
            int jn0 = (jt + 1) << 7;
#pragma unroll
            for (int s = tid; s < 2048; s += 256) {
                int row = s >> 4, q = s & 15;
                CP16(ks_a + (unsigned)(row * QK_STR + q * 4) * 4u,
                     Kz + (long long)(jn0 + row) * DH + q * 4);
            }
            CP_COMMIT();
        }

        // [d] add BD (rel-shift gather from global), scale, mask, softmax
        {
            const float* bdA = BDz + (long long)iA * QLEN + (j0 - iA + QLEN - 1);
            const float* bdB = BDz + (long long)iB * QLEN + (j0 - iB + QLEN - 1);
            bool diag = (jt == it);
#pragma unroll
            for (int ni = 0; ni < 16; ni++) {
                int c0 = ni * 8 + cc * 2;
                float v0 = (s_fr[ni][0] + bdA[c0])     * 0.125f;
                float v1 = (s_fr[ni][1] + bdA[c0 + 1]) * 0.125f;
                float v2 = (s_fr[ni][2] + bdB[c0])     * 0.125f;
                float v3 = (s_fr[ni][3] + bdB[c0 + 1]) * 0.125f;
                if (diag) {
                    if (j0 + c0     > iA) v0 = -1e30f;
                    if (j0 + c0 + 1 > iA) v1 = -1e30f;
                    if (j0 + c0     > iB) v2 = -1e30f;
                    if (j0 + c0 + 1 > iB) v3 = -1e30f;
                }
                s_fr[ni][0] = v0; s_fr[ni][1] = v1;
                s_fr[ni][2] = v2; s_fr[ni][3] = v3;
            }
            // row maxes
            float mxA = -1e30f, mxB = -1e30f;
#pragma unroll
            for (int ni = 0; ni < 16; ni++) {
                mxA = fmaxf(mxA, fmaxf(s_fr[ni][0], s_fr[ni][1]));
                mxB = fmaxf(mxB, fmaxf(s_fr[ni][2], s_fr[ni][3]));
            }
#pragma unroll
            for (int off = 1; off <= 2; off <<= 1) {
                mxA = fmaxf(mxA, __shfl_xor_sync(0xffffffffu, mxA, off));
                mxB = fmaxf(mxB, __shfl_xor_sync(0xffffffffu, mxB, off));
            }
            float mnA = fmaxf(mA, mxA), mnB = fmaxf(mB, mxB);
            float alA = __expf(mA - mnA), alB = __expf(mB - mnB);
            float psA = 0.f, psB = 0.f;
#pragma unroll
            for (int ni = 0; ni < 16; ni++) {
                float p0 = __expf(s_fr[ni][0] - mnA);
                float p1 = __expf(s_fr[ni][1] - mnA);
                float p2 = __expf(s_fr[ni][2] - mnB);
                float p3 = __expf(s_fr[ni][3] - mnB);
                psA += p0 + p1; psB += p2 + p3;
                // write P (RNA tf32) to smem
                int c0 = ni * 8 + cc * 2;
                *(uint2*)(Ps + rowA * VP_STR + c0) = make_uint2(f2tf32(p0), f2tf32(p1));
                *(uint2*)(Ps + (rowA + 8) * VP_STR + c0) = make_uint2(f2tf32(p2), f2tf32(p3));
            }
#pragma unroll
            for (int off = 1; off <= 2; off <<= 1) {
                psA += __shfl_xor_sync(0xffffffffu, psA, off);
                psB += __shfl_xor_sync(0xffffffffu, psB, off);
            }
            mA = mnA; mB = mnB;
            lA = lA * alA + psA; lB = lB * alB + psB;
            // rescale O accumulators
#pragma unroll
            for (int ni = 0; ni < 8; ni++) {
                oacc[ni][0] *= alA; oacc[ni][1] *= alA;
                oacc[ni][2] *= alB; oacc[ni][3] *= alB;
            }
        }

        // [e] wait V(jt), PV MMA
        if (jt < it) { CP_WAIT(1); } else { CP_WAIT(0); }
        __syncthreads();
        {
            const unsigned* Vu = (const unsigned*)Vs;
            int m0 = wid * 16;
#pragma unroll
            for (int ks = 0; ks < 16; ks++) {
                int kb = ks * 8;
                unsigned a0 = Ps[(m0 + r)     * VP_STR + kb + cc];
                unsigned a1 = Ps[(m0 + 8 + r) * VP_STR + kb + cc];
                unsigned a2 = Ps[(m0 + r)     * VP_STR + kb + cc + 4];
                unsigned a3 = Ps[(m0 + 8 + r) * VP_STR + kb + cc + 4];
#pragma unroll
                for (int ni = 0; ni < 8; ni++) {
                    unsigned b0 = Vu[(ni * 8 + r) * VP_STR + kb + cc];
                    unsigned b1 = Vu[(ni * 8 + r) * VP_STR + kb + cc + 4];
                    MMA_TF32(oacc[ni][0], oacc[ni][1], oacc[ni][2], oacc[ni][3],
                             a0, a1, a2, a3, b0, b1);
                }
            }
        }
        __syncthreads();   // Vs/Ps free for next iteration
    }

    // normalize + store
    float invA = 1.f / lA, invB = 1.f / lB;
    long long ta = (long long)iA * BSZ + b;
    long long tb = (long long)iB * BSZ + b;
#pragma unroll
    for (int ni = 0; ni < 8; ni++) {
        int d = ni * 8 + cc * 2;
        *(float2*)(AV + ta * DM + h * 64 + d) =
            make_float2(oacc[ni][0] * invA, oacc[ni][1] * invA);
        *(float2*)(AV + tb * DM + h * 64 + d) =
            make_float2(oacc[ni][2] * invB, oacc[ni][3] * invB);
    }
}

// ---------------- residual + layernorm ----------------
__global__ void __launch_bounds__(256) ln_kernel(
    const float* __restrict__ w, const float* __restrict__ ao,
    const float* __restrict__ g, const float* __restrict__ be,
    float* __restrict__ out)
{
    long long t = blockIdx.x;
    int tid = threadIdx.x;
    __shared__ float red[8];
    __shared__ float s_mu, s_rstd;

    float4 wx = *(const float4*)(w  + t * DM + tid * 4);
    float4 ax = *(const float4*)(ao + t * DM + tid * 4);
    float x0 = wx.x + ax.x, x1 = wx.y + ax.y, x2 = wx.z + ax.z, x3 = wx.w + ax.w;

    float s = x0 + x1 + x2 + x3;
#pragma unroll
    for (int off = 16; off >= 1; off >>= 1) s += __shfl_xor_sync(0xffffffffu, s, off);
    if ((tid & 31) == 0) red[tid >> 5] = s;
    __syncthreads();
    if (tid == 0) {
        float a = 0;
#pragma unroll
        for (int i2 = 0; i2 < 8; i2++) a += red[i2];
        s_mu = a * (1.f / DM);
    }
    __syncthreads();
    float mu = s_mu;
    float d0 = x0 - mu, d1 = x1 - mu, d2 = x2 - mu, d3 = x3 - mu;
    float v = d0 * d0 + d1 * d1 + d2 * d2 + d3 * d3;
#pragma unroll
    for (int off = 16; off >= 1; off >>= 1) v += __shfl_xor_sync(0xffffffffu, v, off);
    if ((tid & 31) == 0) red[tid >> 5] = v;
    __syncthreads();
    if (tid == 0) {
        float a = 0;
#pragma unroll
        for (int i2 = 0; i2 < 8; i2++) a += red[i2];
        s_rstd = rsqrtf(a * (1.f / DM) + 1e-5f);
    }
    __syncthreads();
    float rs = s_rstd;
    float4 gg = *(const float4*)(g  + tid * 4);
    float4 bb = *(const float4*)(be + tid * 4);
    float4 o = make_float4(d0 * rs * gg.x + bb.x, d1 * rs * gg.y + bb.y,
                           d2 * rs * gg.z + bb.z, d3 * rs * gg.w + bb.w);
    *(float4*)(out + t * DM + tid * 4) = o;
}

// ---------------- host launcher ----------------
extern "C" void kernel_launch(void* const* d_in, const int* in_sizes, int n_in,
                              void* d_out, int out_size)
{
    const float* w       = (const float*)d_in[0];
    const float* r       = (const float*)d_in[1];
    const float* rwb     = (const float*)d_in[2];
    const float* rrb     = (const float*)d_in[3];
    const float* qkv_w   = (const float*)d_in[4];
    const float* r_net_w = (const float*)d_in[5];
    const float* o_w     = (const float*)d_in[6];
    const float* gamma   = (const float*)d_in[7];
    const float* beta    = (const float*)d_in[8];
    float* out = (float*)d_out;

    float *wheads, *rkraw, *QW, *QR, *Kb, *Vb, *RK, *BD, *AV, *AO;
    cudaGetSymbolAddress((void**)&wheads, g_wheads);
    cudaGetSymbolAddress((void**)&rkraw,  g_rkraw);
    cudaGetSymbolAddress((void**)&QW, g_QW);
    cudaGetSymbolAddress((void**)&QR, g_QR);
    cudaGetSymbolAddress((void**)&Kb, g_Kb);
    cudaGetSymbolAddress((void**)&Vb, g_Vb);
    cudaGetSymbolAddress((void**)&RK, g_RK);
    cudaGetSymbolAddress((void**)&BD, g_BD);
    cudaGetSymbolAddress((void**)&AV, g_AV);
    cudaGetSymbolAddress((void**)&AO, g_AO);

    cudaFuncSetAttribute(gemm_mma_kernel, cudaFuncAttributeMaxDynamicSharedMemorySize, GEMM_SMEM);
    cudaFuncSetAttribute(attn_kernel, cudaFuncAttributeMaxDynamicSharedMemorySize, ATTN_SMEM);

    // 1) w_heads = w @ qkv_w^T   [4096 x 3072]
    gemm_mma_kernel<<<dim3(3072 / 128, T_TOK / 128, 1), 256, GEMM_SMEM>>>(
        w, qkv_w, wheads, T_TOK, 3072, DM, 0, 0, 0, 0);
    // 2) r_head_k = r @ r_net_w^T   [4096 x 1024]
    gemm_mma_kernel<<<dim3(DM / 128, T_TOK / 128, 1), 256, GEMM_SMEM>>>(
        r, r_net_w, rkraw, T_TOK, DM, DM, 0, 0, 0, 0);
    // 3) split + biases (pre-round to tf32)
    split_kernel<<<(NZ * QLEN * DH) / 256, 256>>>(wheads, rkraw, rwb, rrb, QW, QR, Kb, Vb, RK);
    // 4) BD = (q+rrb) . rk   batched, band tiles
    gemm_mma_kernel<<<dim3(QLEN / 128, QLEN / 128, NZ), 256, GEMM_SMEM>>>(
        QR, RK, BD, QLEN, QLEN, DH,
        (long long)QLEN * DH, (long long)QLEN * DH, (long long)QLEN * QLEN, 2);
    // 5) semi-fused attention: AC on MMA in-kernel + BD gather + softmax + PV
    attn_kernel<<<dim3(QLEN / 128, NZ), 256, ATTN_SMEM>>>(BD, Kb, Vb, QW, AV);
    // 6) attn_out = AV @ o_w^T
    gemm_mma_kernel<<<dim3(DM / 128, T_TOK / 128, 1), 256, GEMM_SMEM>>>(
        AV, o_w, AO, T_TOK, DM, DM, 0, 0, 0, 0);
    // 7) residual + layernorm -> out
    ln_kernel<<<T_TOK, 256>>>(w, AO, gamma, beta, out);
}